// round 1
// baseline (speedup 1.0000x reference)
#include <cuda_runtime.h>
#include <math.h>

// ---------------- scratch (device globals; no allocation) ----------------
__device__ float g_gi[125829120];   // max(327680, 65536, 2048) rows x 384
__device__ float g_hist[41943040];  // max(65536*5, 2048*32, 2048*1) x 128
__device__ float g_short[8388608];  // 65536 x 128
__device__ float g_WT[49152];       // transposed Whh: [k][g] = 128 x 384
__device__ float g_intra[262144];   // 2048 x 128
__device__ float g_lg[262144];
__device__ float g_la[262144];
__device__ float g_Wh[262144];      // GAT intra Wh
__device__ float g_s12[4096];       // s1 (2048) + s2 (2048)
__device__ float g_sec[2048];       // 16 x 128
__device__ float g_Wh2[2048];
__device__ float g_s12b[32];
__device__ float g_secout[2048];

// ---------------- helpers ----------------
__device__ __forceinline__ float sigmoidf_(float x) {
    return __fdividef(1.f, 1.f + __expf(-x));
}
__device__ __forceinline__ float tanhf_(float x) {
    return 2.f * sigmoidf_(2.f * x) - 1.f;
}
// 128-thread block sum; red must be shared float[4]
__device__ __forceinline__ float blockReduceSum128(float v, float* red) {
    #pragma unroll
    for (int o = 16; o; o >>= 1) v += __shfl_xor_sync(0xffffffffu, v, o);
    int w = threadIdx.x >> 5;
    if ((threadIdx.x & 31) == 0) red[w] = v;
    __syncthreads();
    float s = red[0] + red[1] + red[2] + red[3];
    __syncthreads();
    return s;
}

// ---------------- C[M,384] = A[M,K] @ W[384,K]^T + bias ----------------
// grid (M/64, 6), block 256. K in {16,128}, multiples handled exactly.
__global__ void __launch_bounds__(256) gemm_bias(
    const float* __restrict__ A, const float* __restrict__ W,
    const float* __restrict__ bias, float* __restrict__ C, int K)
{
    __shared__ float As[16][64];
    __shared__ float Ws[16][64];
    int tid = threadIdx.x;
    int tx = tid & 15, ty = tid >> 4;
    size_t m0 = (size_t)blockIdx.x * 64;
    int n0 = blockIdx.y * 64;
    float acc[16];
    #pragma unroll
    for (int q = 0; q < 16; q++) acc[q] = 0.f;
    int r = tid >> 2, cg = (tid & 3) * 4;
    for (int kc = 0; kc < K; kc += 16) {
        float4 av = *(const float4*)(A + (m0 + r) * K + kc + cg);
        As[cg + 0][r] = av.x; As[cg + 1][r] = av.y; As[cg + 2][r] = av.z; As[cg + 3][r] = av.w;
        float4 wv = *(const float4*)(W + (size_t)(n0 + r) * K + kc + cg);
        Ws[cg + 0][r] = wv.x; Ws[cg + 1][r] = wv.y; Ws[cg + 2][r] = wv.z; Ws[cg + 3][r] = wv.w;
        __syncthreads();
        #pragma unroll
        for (int kk = 0; kk < 16; kk++) {
            float4 a4 = *(const float4*)&As[kk][ty * 4];
            float4 w4 = *(const float4*)&Ws[kk][tx * 4];
            acc[0]  = fmaf(a4.x, w4.x, acc[0]);  acc[1]  = fmaf(a4.x, w4.y, acc[1]);
            acc[2]  = fmaf(a4.x, w4.z, acc[2]);  acc[3]  = fmaf(a4.x, w4.w, acc[3]);
            acc[4]  = fmaf(a4.y, w4.x, acc[4]);  acc[5]  = fmaf(a4.y, w4.y, acc[5]);
            acc[6]  = fmaf(a4.y, w4.z, acc[6]);  acc[7]  = fmaf(a4.y, w4.w, acc[7]);
            acc[8]  = fmaf(a4.z, w4.x, acc[8]);  acc[9]  = fmaf(a4.z, w4.y, acc[9]);
            acc[10] = fmaf(a4.z, w4.z, acc[10]); acc[11] = fmaf(a4.z, w4.w, acc[11]);
            acc[12] = fmaf(a4.w, w4.x, acc[12]); acc[13] = fmaf(a4.w, w4.y, acc[13]);
            acc[14] = fmaf(a4.w, w4.z, acc[14]); acc[15] = fmaf(a4.w, w4.w, acc[15]);
        }
        __syncthreads();
    }
    const float4 bv = *(const float4*)&bias[n0 + tx * 4];
    #pragma unroll
    for (int mi = 0; mi < 4; mi++) {
        float4 cv;
        cv.x = acc[mi * 4 + 0] + bv.x;
        cv.y = acc[mi * 4 + 1] + bv.y;
        cv.z = acc[mi * 4 + 2] + bv.z;
        cv.w = acc[mi * 4 + 3] + bv.w;
        *(float4*)(C + (m0 + ty * 4 + mi) * 384 + n0 + tx * 4) = cv;
    }
}

// ---------------- transpose Whh[384,128] -> WT[k*384+g] ----------------
__global__ void transpose_whh(const float* __restrict__ Whh, float* __restrict__ WT) {
    int g = blockIdx.x, k = threadIdx.x;
    WT[k * 384 + g] = Whh[g * 128 + k];
}

// ---------------- GRU recurrence ----------------
// gi[batch,T,384] already holds x@Wih^T + bih. hist[batch,T,128] gets all h_t.
// block = 512 threads = 128 j-lanes x 4 seq-groups; 16 sequences per CTA.
__global__ void __launch_bounds__(512) gru_rec(
    const float* __restrict__ gi, const float* __restrict__ WT,
    const float* __restrict__ bhh, float* __restrict__ hist, int T)
{
    __shared__ float sh[16 * 128];
    int tid = threadIdx.x;
    int jt = tid & 127, sg = tid >> 7;
    for (int idx = tid; idx < 2048; idx += 512) sh[idx] = 0.f;
    float br = __ldg(bhh + jt);
    float bz = __ldg(bhh + jt + 128);
    float bn = __ldg(bhh + jt + 256);
    size_t seq0 = (size_t)blockIdx.x * 16 + sg * 4;
    __syncthreads();

    for (int t = 0; t < T; t++) {
        float ar[4] = {0.f, 0.f, 0.f, 0.f};
        float az[4] = {0.f, 0.f, 0.f, 0.f};
        float an[4] = {0.f, 0.f, 0.f, 0.f};
        if (t > 0) {
            const float* WTj = WT + jt;
            #pragma unroll 4
            for (int k = 0; k < 128; k++) {
                float wr = __ldg(WTj + k * 384);
                float wz = __ldg(WTj + k * 384 + 128);
                float wn = __ldg(WTj + k * 384 + 256);
                #pragma unroll
                for (int i = 0; i < 4; i++) {
                    float h = sh[(sg * 4 + i) * 128 + k];
                    ar[i] = fmaf(wr, h, ar[i]);
                    az[i] = fmaf(wz, h, az[i]);
                    an[i] = fmaf(wn, h, an[i]);
                }
            }
        }
        float hnew[4];
        #pragma unroll
        for (int i = 0; i < 4; i++) {
            const float* gp = gi + ((seq0 + i) * T + t) * 384;
            float gr = __ldcs(gp + jt);
            float gz = __ldcs(gp + jt + 128);
            float gn = __ldcs(gp + jt + 256);
            float rr = sigmoidf_(gr + ar[i] + br);
            float zz = sigmoidf_(gz + az[i] + bz);
            float nn = tanhf_(fmaf(rr, an[i] + bn, gn));
            float hold = sh[(sg * 4 + i) * 128 + jt];
            hnew[i] = (1.f - zz) * nn + zz * hold;
        }
        __syncthreads();
        #pragma unroll
        for (int i = 0; i < 4; i++) {
            sh[(sg * 4 + i) * 128 + jt] = hnew[i];
            __stcs(hist + ((seq0 + i) * T + t) * 128 + jt, hnew[i]);
        }
        __syncthreads();
    }
}

// ---------------- attention pooling over T ----------------
// grid = batch, block 128. out[s,128] = sum_t softmax(h_t@aw+ab)_t * h_t
__global__ void __launch_bounds__(128) attn_pool(
    const float* __restrict__ hist, const float* __restrict__ aw,
    const float* __restrict__ ab, float* __restrict__ out, int T)
{
    __shared__ float red[4];
    __shared__ float sc[32];
    int s = blockIdx.x, d = threadIdx.x;
    const float* hp = hist + (size_t)s * T * 128;
    float a = __ldg(aw + d);
    float ab0 = __ldg(ab);
    for (int t = 0; t < T; t++) {
        float v = hp[t * 128 + d] * a;
        float sum = blockReduceSum128(v, red);
        if (d == 0) sc[t] = sum + ab0;
    }
    __syncthreads();
    float m = -1e30f;
    for (int t = 0; t < T; t++) m = fmaxf(m, sc[t]);
    float Z = 0.f, acc = 0.f;
    for (int t = 0; t < T; t++) {
        float w = __expf(sc[t] - m);
        Z += w;
        acc = fmaf(w, hp[t * 128 + d], acc);
    }
    out[(size_t)s * 128 + d] = acc / Z;
}

// ---------------- GAT prep: Wh = H@W, s1 = Wh@a1, s2 = Wh@a2 ----------------
__global__ void __launch_bounds__(128) gat_prep(
    const float* __restrict__ Hin, int rstride,
    const float* __restrict__ W, const float* __restrict__ a,
    float* __restrict__ Wh, float* __restrict__ s12, int M)
{
    __shared__ float red[4];
    int m = blockIdx.x, n = threadIdx.x;
    const float* hr = Hin + (size_t)m * rstride;
    float acc = 0.f;
    #pragma unroll 8
    for (int k = 0; k < 128; k++) acc = fmaf(__ldg(hr + k), W[k * 128 + n], acc);
    Wh[(size_t)m * 128 + n] = acc;
    float s1 = blockReduceSum128(acc * __ldg(a + n), red);
    float s2 = blockReduceSum128(acc * __ldg(a + 128 + n), red);
    if (n == 0) { s12[m] = s1; s12[M + m] = s2; }
}

// ---------------- GAT intra attention (sector mask, 2048 nodes) ----------------
__global__ void __launch_bounds__(128) gat_intra_attn(
    const float* __restrict__ Wh, const float* __restrict__ s12,
    const int* __restrict__ sect, float* __restrict__ out)
{
    __shared__ float red[4];
    __shared__ int lst[2048];
    __shared__ float wgt[2048];
    __shared__ int cnt;
    int i = blockIdx.x, d = threadIdx.x;
    if (d == 0) cnt = 0;
    __syncthreads();
    int si = __ldg(sect + i);
    for (int j = d; j < 2048; j += 128)
        if (__ldg(sect + j) == si) { int p = atomicAdd(&cnt, 1); lst[p] = j; }
    __syncthreads();
    int n = cnt;
    float s1i = s12[i];
    float lm = -1e30f;
    for (int p = d; p < n; p += 128) {
        float e = s1i + s12[2048 + lst[p]];
        e = e >= 0.f ? e : 0.2f * e;
        lm = fmaxf(lm, e);
    }
    #pragma unroll
    for (int o = 16; o; o >>= 1) lm = fmaxf(lm, __shfl_xor_sync(0xffffffffu, lm, o));
    if ((d & 31) == 0) red[d >> 5] = lm;
    __syncthreads();
    float m = fmaxf(fmaxf(red[0], red[1]), fmaxf(red[2], red[3]));
    __syncthreads();
    float lz = 0.f;
    for (int p = d; p < n; p += 128) {
        float e = s1i + s12[2048 + lst[p]];
        e = e >= 0.f ? e : 0.2f * e;
        float w = __expf(e - m);
        wgt[p] = w;
        lz += w;
    }
    float Z = blockReduceSum128(lz, red);
    float inv = __fdividef(1.f, Z);
    float acc = 0.f;
    #pragma unroll 4
    for (int p = 0; p < n; p++) acc = fmaf(wgt[p], Wh[(size_t)lst[p] * 128 + d], acc);
    acc *= inv;
    out[(size_t)i * 128 + d] = acc > 0.f ? acc : expm1f(acc);
}

// ---------------- sector mean ----------------
__global__ void __launch_bounds__(128) sector_mean(
    const float* __restrict__ lg, const int* __restrict__ sect, float* __restrict__ sec)
{
    int ns = blockIdx.x, d = threadIdx.x;
    float s = 0.f;
    int c = 0;
    for (int i = 0; i < 2048; i++) {
        if (__ldg(sect + i) == ns) { s += lg[(size_t)i * 128 + d]; c++; }
    }
    sec[ns * 128 + d] = s / fmaxf((float)c, 1.f);
}

// ---------------- GAT inter attention (16 nodes, adjacency mask) ----------------
__global__ void __launch_bounds__(128) gat_inter_attn(
    const float* __restrict__ Wh, const float* __restrict__ s12,
    const int* __restrict__ adj, float* __restrict__ out)
{
    __shared__ float e[16];
    int i = blockIdx.x, d = threadIdx.x;
    if (d < 16) {
        float v = s12[i] + s12[16 + d];
        v = v >= 0.f ? v : 0.2f * v;
        e[d] = (__ldg(adj + i * 16 + d) > 0) ? v : -9.0e15f;
    }
    __syncthreads();
    float m = -1e30f;
    #pragma unroll
    for (int j = 0; j < 16; j++) m = fmaxf(m, e[j]);
    float Z = 0.f, acc = 0.f;
    #pragma unroll
    for (int j = 0; j < 16; j++) {
        float w = __expf(e[j] - m);
        Z += w;
        acc = fmaf(w, Wh[j * 128 + d], acc);
    }
    acc = __fdividef(acc, Z);
    out[i * 128 + d] = acc > 0.f ? acc : expm1f(acc);
}

// ---------------- fusion + heads ----------------
__global__ void __launch_bounds__(128) fusion_heads(
    const float* __restrict__ lg, const float* __restrict__ la,
    const float* __restrict__ secout, const int* __restrict__ sect,
    const float* __restrict__ fw, const float* __restrict__ fb,
    const float* __restrict__ rw, const float* __restrict__ rb,
    const float* __restrict__ mw, const float* __restrict__ mb,
    float* __restrict__ out)
{
    __shared__ float red[4];
    int i = blockIdx.x, n = threadIdx.x;
    int si = __ldg(sect + i);
    const float* lgr = lg + (size_t)i * 128;
    const float* lar = la + (size_t)i * 128;
    const float* ser = secout + (size_t)si * 128;
    float acc = __ldg(fb + n);
    #pragma unroll 4
    for (int k = 0; k < 128; k++) acc = fmaf(__ldg(lgr + k), fw[k * 128 + n], acc);
    #pragma unroll 4
    for (int k = 0; k < 128; k++) acc = fmaf(__ldg(lar + k), fw[(128 + k) * 128 + n], acc);
    #pragma unroll 4
    for (int k = 0; k < 128; k++) acc = fmaf(__ldg(ser + k), fw[(256 + k) * 128 + n], acc);
    float r  = blockReduceSum128(acc * __ldg(rw + n), red);
    float mv = blockReduceSum128(acc * __ldg(mw + n), red);
    if (n == 0) {
        out[i]        = r + __ldg(rb);
        out[2048 + i] = sigmoidf_(mv + __ldg(mb));
    }
}

// ---------------- launch ----------------
extern "C" void kernel_launch(void* const* d_in, const int* in_sizes, int n_in,
                              void* d_out, int out_size)
{
    const float* sf    = (const float*)d_in[0];
    const int*   sect  = (const int*)d_in[1];
    const int*   adj   = (const int*)d_in[2];
    const float* g1Wih = (const float*)d_in[3];
    const float* g1Whh = (const float*)d_in[4];
    const float* g1bih = (const float*)d_in[5];
    const float* g1bhh = (const float*)d_in[6];
    const float* a1w   = (const float*)d_in[7];
    const float* a1b   = (const float*)d_in[8];
    const float* giW   = (const float*)d_in[9];
    const float* gia   = (const float*)d_in[10];
    const float* ggWih = (const float*)d_in[11];
    const float* ggWhh = (const float*)d_in[12];
    const float* ggbih = (const float*)d_in[13];
    const float* ggbhh = (const float*)d_in[14];
    const float* agw   = (const float*)d_in[15];
    const float* agb   = (const float*)d_in[16];
    const float* gaWih = (const float*)d_in[17];
    const float* gaWhh = (const float*)d_in[18];
    const float* gabih = (const float*)d_in[19];
    const float* gabhh = (const float*)d_in[20];
    const float* aaw   = (const float*)d_in[21];
    const float* aab   = (const float*)d_in[22];
    const float* geW   = (const float*)d_in[23];
    const float* gea   = (const float*)d_in[24];
    const float* fw    = (const float*)d_in[25];
    const float* fb    = (const float*)d_in[26];
    const float* rw    = (const float*)d_in[27];
    const float* rb    = (const float*)d_in[28];
    const float* mw    = (const float*)d_in[29];
    const float* mb    = (const float*)d_in[30];
    float* out = (float*)d_out;

    float *gi, *hist, *shortb, *WT, *intra, *lgv, *lav, *Wh, *s12, *sec, *Wh2, *s12b, *secout;
    cudaGetSymbolAddress((void**)&gi, g_gi);
    cudaGetSymbolAddress((void**)&hist, g_hist);
    cudaGetSymbolAddress((void**)&shortb, g_short);
    cudaGetSymbolAddress((void**)&WT, g_WT);
    cudaGetSymbolAddress((void**)&intra, g_intra);
    cudaGetSymbolAddress((void**)&lgv, g_lg);
    cudaGetSymbolAddress((void**)&lav, g_la);
    cudaGetSymbolAddress((void**)&Wh, g_Wh);
    cudaGetSymbolAddress((void**)&s12, g_s12);
    cudaGetSymbolAddress((void**)&sec, g_sec);
    cudaGetSymbolAddress((void**)&Wh2, g_Wh2);
    cudaGetSymbolAddress((void**)&s12b, g_s12b);
    cudaGetSymbolAddress((void**)&secout, g_secout);

    // Stage 1: GRU1 over 65536 sequences (T=5, F=16)
    gemm_bias<<<dim3(327680 / 64, 6), 256>>>(sf, g1Wih, g1bih, gi, 16);
    transpose_whh<<<384, 128>>>(g1Whh, WT);
    gru_rec<<<4096, 512>>>(gi, WT, g1bhh, hist, 5);
    attn_pool<<<65536, 128>>>(hist, a1w, a1b, shortb, 5);

    // Stage 2: intra-sector GAT on last week's embedding
    gat_prep<<<2048, 128>>>(shortb + 31 * 128, 32 * 128, giW, gia, Wh, s12, 2048);
    gat_intra_attn<<<2048, 128>>>(Wh, s12, sect, intra);

    // Stage 3: lg = single-step GRU on intra (T=1)
    gemm_bias<<<dim3(2048 / 64, 6), 256>>>(intra, ggWih, ggbih, gi, 128);
    transpose_whh<<<384, 128>>>(ggWhh, WT);
    gru_rec<<<128, 512>>>(gi, WT, ggbhh, hist, 1);
    attn_pool<<<2048, 128>>>(hist, agw, agb, lgv, 1);

    // Stage 4: la = GRU over 32 weekly embeddings (T=32, F=128)
    gemm_bias<<<dim3(65536 / 64, 6), 256>>>(shortb, gaWih, gabih, gi, 128);
    transpose_whh<<<384, 128>>>(gaWhh, WT);
    gru_rec<<<128, 512>>>(gi, WT, gabhh, hist, 32);
    attn_pool<<<2048, 128>>>(hist, aaw, aab, lav, 32);

    // Stage 5: sector aggregation + inter-sector GAT
    sector_mean<<<16, 128>>>(lgv, sect, sec);
    gat_prep<<<16, 128>>>(sec, 128, geW, gea, Wh2, s12b, 16);
    gat_inter_attn<<<16, 128>>>(Wh2, s12b, adj, secout);

    // Stage 6: fusion + heads
    fusion_heads<<<2048, 128>>>(lgv, lav, secout, sect, fw, fb, rw, rb, mw, mb, out);
}

// round 3
// speedup vs baseline: 2.0118x; 2.0118x over previous
#include <cuda_runtime.h>
#include <math.h>

// ---------------- scratch (device globals; no allocation) ----------------
__device__ float g_gi[25165824];    // 65536 x 384 (stage4 gi; stage3 uses prefix)
__device__ float g_hist[8388608];   // 2048 x 32 x 128 (stage4 hist)
__device__ float g_short[8388608];  // 65536 x 128
__device__ float g_WT1[49152];      // Whh1^T [128][384]
__device__ float g_WiT[6144];       // Wih1^T [16][384]
__device__ float g_WT4[49152];      // gaWhh^T [128][384]
__device__ float g_intra[262144];   // 2048 x 128
__device__ float g_lg[262144];
__device__ float g_la[262144];
__device__ float g_Wh[262144];
__device__ float g_s12[4096];
__device__ float g_sec[2048];
__device__ float g_Wh2[2048];
__device__ float g_s12b[32];
__device__ float g_secout[2048];

// ---------------- helpers ----------------
__device__ __forceinline__ float sigmoidf_(float x) {
    return __fdividef(1.f, 1.f + __expf(-x));
}
__device__ __forceinline__ float tanhf_(float x) {
    return 2.f * sigmoidf_(2.f * x) - 1.f;
}
__device__ __forceinline__ unsigned f2tf(float f) {
    unsigned u; asm("cvt.rna.tf32.f32 %0, %1;" : "=r"(u) : "f"(f)); return u;
}
__device__ __forceinline__ void mma_tf32(float d[4], const unsigned a[4],
                                         unsigned b0, unsigned b1) {
    asm volatile(
        "mma.sync.aligned.m16n8k8.row.col.f32.tf32.tf32.f32 "
        "{%0,%1,%2,%3},{%4,%5,%6,%7},{%8,%9},{%0,%1,%2,%3};\n"
        : "+f"(d[0]), "+f"(d[1]), "+f"(d[2]), "+f"(d[3])
        : "r"(a[0]), "r"(a[1]), "r"(a[2]), "r"(a[3]), "r"(b0), "r"(b1));
}
__device__ __forceinline__ float blockReduceSum128(float v, float* red) {
    #pragma unroll
    for (int o = 16; o; o >>= 1) v += __shfl_xor_sync(0xffffffffu, v, o);
    int w = threadIdx.x >> 5;
    if ((threadIdx.x & 31) == 0) red[w] = v;
    __syncthreads();
    float s = red[0] + red[1] + red[2] + red[3];
    __syncthreads();
    return s;
}

// ---------------- transpose W[384,K] -> WT[k*384+g] ----------------
__global__ void transpose_w(const float* __restrict__ W, float* __restrict__ WT, int K) {
    int g = blockIdx.x, k = threadIdx.x;
    WT[k * 384 + g] = W[g * K + k];
}

// ---------------- tensor-core GRU recurrence ----------------
// 16 seqs/CTA, 512 threads = 16 warps. Warp w owns output cols {w*8+nt*128}.
// Whh^T fragments resident in registers (96/thread).
// XMMA: gi computed on the fly from x (rows of 80 = [5][16]) via tf32 mma.
// FUSE: h history kept in smem, attention pooling fused (T<=5).
template<int T, bool XMMA, bool FUSE>
__global__ void __launch_bounds__(512, 1) gru_mma(
    const float* __restrict__ xin,   // XMMA: x rows of 80; else gi [(seq*T+t)][384]
    const float* __restrict__ WiT,   // XMMA: [16][384]
    const float* __restrict__ WT,    // [128][384]
    const float* __restrict__ bih,   // XMMA only
    const float* __restrict__ bhh,
    const float* __restrict__ aw, const float* __restrict__ ab,  // FUSE only
    float* __restrict__ outp)        // FUSE: [seq][128]; else hist [(seq*T+t)][128]
{
    extern __shared__ float sm[];
    constexpr int HT = FUSE ? T : 1;
    float* hist_s = sm;                          // HT*16*132
    float* gh_s   = hist_s + HT * 16 * 132;      // 16*392
    float* gin_s  = gh_s + 16 * 392;             // 16*136 (XMMA)
    float* x_s    = gin_s + (XMMA ? 16 * 136 : 0);
    float* sc_s   = x_s + (XMMA ? 16 * 84 : 0);  // 16*8 (FUSE)

    int tid = threadIdx.x;
    int w = tid >> 5, lane = tid & 31;
    int g = lane >> 2, tig = lane & 3;
    size_t seq0 = (size_t)blockIdx.x * 16;

    if (XMMA) {
        for (int i = tid; i < 16 * 80; i += 512)
            x_s[(i / 80) * 84 + (i % 80)] = __ldg(xin + seq0 * 80 + i);
    }

    // Load Whh^T fragments into registers (tf32)
    unsigned wb[16][3][2];
    #pragma unroll
    for (int kt = 0; kt < 16; kt++) {
        #pragma unroll
        for (int nt = 0; nt < 3; nt++) {
            int col = nt * 128 + w * 8 + g;
            wb[kt][nt][0] = f2tf(__ldg(WT + (kt * 8 + tig) * 384 + col));
            wb[kt][nt][1] = f2tf(__ldg(WT + (kt * 8 + tig + 4) * 384 + col));
        }
    }
    __syncthreads();

    for (int t = 0; t < T; t++) {
        float ar[4] = {0, 0, 0, 0}, az[4] = {0, 0, 0, 0};
        float an[4] = {0, 0, 0, 0}, agn[4] = {0, 0, 0, 0};

        if (XMMA) {
            // gi = x @ Wih^T (K=16): r,z merged into ar/az; n kept separate in agn
            #pragma unroll
            for (int kt = 0; kt < 2; kt++) {
                unsigned a[4];
                int kc = t * 16 + kt * 8 + tig;
                a[0] = f2tf(x_s[g * 84 + kc]);
                a[1] = f2tf(x_s[(g + 8) * 84 + kc]);
                a[2] = f2tf(x_s[g * 84 + kc + 4]);
                a[3] = f2tf(x_s[(g + 8) * 84 + kc + 4]);
                #pragma unroll
                for (int nt = 0; nt < 3; nt++) {
                    int col = nt * 128 + w * 8 + g;
                    unsigned b0 = f2tf(__ldg(WiT + (kt * 8 + tig) * 384 + col));
                    unsigned b1 = f2tf(__ldg(WiT + (kt * 8 + tig + 4) * 384 + col));
                    mma_tf32(nt == 0 ? ar : (nt == 1 ? az : agn), a, b0, b1);
                }
            }
        }
        if (t > 0) {
            const float* hp = hist_s + (FUSE ? (t - 1) * 16 * 132 : 0);
            #pragma unroll
            for (int kt = 0; kt < 16; kt++) {
                unsigned a[4];
                int kc = kt * 8 + tig;
                a[0] = f2tf(hp[g * 132 + kc]);
                a[1] = f2tf(hp[(g + 8) * 132 + kc]);
                a[2] = f2tf(hp[g * 132 + kc + 4]);
                a[3] = f2tf(hp[(g + 8) * 132 + kc + 4]);
                mma_tf32(ar, a, wb[kt][0][0], wb[kt][0][1]);
                mma_tf32(az, a, wb[kt][1][0], wb[kt][1][1]);
                mma_tf32(an, a, wb[kt][2][0], wb[kt][2][1]);
            }
        }
        // store fragments to smem
        {
            int c0 = w * 8 + 2 * tig;
            gh_s[g * 392 + c0]             = ar[0]; gh_s[g * 392 + c0 + 1]       = ar[1];
            gh_s[(g + 8) * 392 + c0]       = ar[2]; gh_s[(g + 8) * 392 + c0 + 1] = ar[3];
            gh_s[g * 392 + 128 + c0]       = az[0]; gh_s[g * 392 + 128 + c0 + 1] = az[1];
            gh_s[(g + 8) * 392 + 128 + c0] = az[2]; gh_s[(g + 8) * 392 + 128 + c0 + 1] = az[3];
            gh_s[g * 392 + 256 + c0]       = an[0]; gh_s[g * 392 + 256 + c0 + 1] = an[1];
            gh_s[(g + 8) * 392 + 256 + c0] = an[2]; gh_s[(g + 8) * 392 + 256 + c0 + 1] = an[3];
            if (XMMA) {
                gin_s[g * 136 + c0]       = agn[0]; gin_s[g * 136 + c0 + 1]       = agn[1];
                gin_s[(g + 8) * 136 + c0] = agn[2]; gin_s[(g + 8) * 136 + c0 + 1] = agn[3];
            }
        }
        __syncthreads();

        // elementwise gate update: thread -> j = tid&127, seqs {sb, sb+4, sb+8, sb+12}
        {
            int j = tid & 127, sb = tid >> 7;
            float* hcur = hist_s + (FUSE ? t * 16 * 132 : 0);
            const float* hpv = hist_s + (FUSE ? (t > 0 ? t - 1 : 0) * 16 * 132 : 0);
            float bir = 0.f, biz = 0.f, bin = 0.f;
            if (XMMA) {
                bir = __ldg(bih + j); biz = __ldg(bih + 128 + j); bin = __ldg(bih + 256 + j);
            }
            float bhr = __ldg(bhh + j), bhz = __ldg(bhh + 128 + j), bhn = __ldg(bhh + 256 + j);
            #pragma unroll
            for (int i = 0; i < 4; i++) {
                int s = sb + i * 4;
                float gr = gh_s[s * 392 + j];
                float gz = gh_s[s * 392 + 128 + j];
                float gnh = gh_s[s * 392 + 256 + j];
                float gin;
                if (XMMA) {
                    gin = gin_s[s * 136 + j] + bin;
                } else {
                    const float* gp = xin + ((seq0 + s) * T + t) * 384;
                    gr += __ldcs(gp + j);
                    gz += __ldcs(gp + 128 + j);
                    gin = __ldcs(gp + 256 + j);
                }
                float r = sigmoidf_(gr + bir + bhr);
                float z = sigmoidf_(gz + biz + bhz);
                float n = tanhf_(gin + r * (gnh + bhn));
                float hold = (t == 0) ? 0.f : hpv[s * 132 + j];
                float hnew = (1.f - z) * n + z * hold;
                hcur[s * 132 + j] = hnew;
                if (!FUSE) __stcs(outp + ((seq0 + s) * T + t) * 128 + j, hnew);
            }
        }
        __syncthreads();
    }

    if (FUSE) {
        // fused attention pooling over T
        float ab0 = __ldg(ab);
        {
            int s = w;  // 16 warps = 16 seqs
            for (int t = 0; t < T; t++) {
                float v = 0.f;
                #pragma unroll
                for (int q = 0; q < 4; q++) {
                    int j = lane + 32 * q;
                    v = fmaf(hist_s[t * 16 * 132 + s * 132 + j], __ldg(aw + j), v);
                }
                #pragma unroll
                for (int o = 16; o; o >>= 1) v += __shfl_xor_sync(0xffffffffu, v, o);
                if (lane == 0) sc_s[s * 8 + t] = v + ab0;
            }
        }
        __syncthreads();
        int j = tid & 127, sb = tid >> 7;
        #pragma unroll
        for (int i = 0; i < 4; i++) {
            int s = sb + i * 4;
            float m = -1e30f;
            #pragma unroll
            for (int t = 0; t < T; t++) m = fmaxf(m, sc_s[s * 8 + t]);
            float Z = 0.f, acc = 0.f;
            #pragma unroll
            for (int t = 0; t < T; t++) {
                float wt = __expf(sc_s[s * 8 + t] - m);
                Z += wt;
                acc = fmaf(wt, hist_s[t * 16 * 132 + s * 132 + j], acc);
            }
            outp[(seq0 + s) * 128 + j] = acc / Z;
        }
    }
}

// ---------------- C[M,384] = A[M,K] @ W[384,K]^T + bias (SIMT fp32) ----------------
__global__ void __launch_bounds__(256) gemm_bias(
    const float* __restrict__ A, const float* __restrict__ W,
    const float* __restrict__ bias, float* __restrict__ C, int K)
{
    __shared__ float As[16][64];
    __shared__ float Ws[16][64];
    int tid = threadIdx.x;
    int tx = tid & 15, ty = tid >> 4;
    size_t m0 = (size_t)blockIdx.x * 64;
    int n0 = blockIdx.y * 64;
    float acc[16];
    #pragma unroll
    for (int q = 0; q < 16; q++) acc[q] = 0.f;
    int r = tid >> 2, cg = (tid & 3) * 4;
    for (int kc = 0; kc < K; kc += 16) {
        float4 av = *(const float4*)(A + (m0 + r) * K + kc + cg);
        As[cg + 0][r] = av.x; As[cg + 1][r] = av.y; As[cg + 2][r] = av.z; As[cg + 3][r] = av.w;
        float4 wv = *(const float4*)(W + (size_t)(n0 + r) * K + kc + cg);
        Ws[cg + 0][r] = wv.x; Ws[cg + 1][r] = wv.y; Ws[cg + 2][r] = wv.z; Ws[cg + 3][r] = wv.w;
        __syncthreads();
        #pragma unroll
        for (int kk = 0; kk < 16; kk++) {
            float4 a4 = *(const float4*)&As[kk][ty * 4];
            float4 w4 = *(const float4*)&Ws[kk][tx * 4];
            acc[0]  = fmaf(a4.x, w4.x, acc[0]);  acc[1]  = fmaf(a4.x, w4.y, acc[1]);
            acc[2]  = fmaf(a4.x, w4.z, acc[2]);  acc[3]  = fmaf(a4.x, w4.w, acc[3]);
            acc[4]  = fmaf(a4.y, w4.x, acc[4]);  acc[5]  = fmaf(a4.y, w4.y, acc[5]);
            acc[6]  = fmaf(a4.y, w4.z, acc[6]);  acc[7]  = fmaf(a4.y, w4.w, acc[7]);
            acc[8]  = fmaf(a4.z, w4.x, acc[8]);  acc[9]  = fmaf(a4.z, w4.y, acc[9]);
            acc[10] = fmaf(a4.z, w4.z, acc[10]); acc[11] = fmaf(a4.z, w4.w, acc[11]);
            acc[12] = fmaf(a4.w, w4.x, acc[12]); acc[13] = fmaf(a4.w, w4.y, acc[13]);
            acc[14] = fmaf(a4.w, w4.z, acc[14]); acc[15] = fmaf(a4.w, w4.w, acc[15]);
        }
        __syncthreads();
    }
    const float4 bv = *(const float4*)&bias[n0 + tx * 4];
    #pragma unroll
    for (int mi = 0; mi < 4; mi++) {
        float4 cv;
        cv.x = acc[mi * 4 + 0] + bv.x;
        cv.y = acc[mi * 4 + 1] + bv.y;
        cv.z = acc[mi * 4 + 2] + bv.z;
        cv.w = acc[mi * 4 + 3] + bv.w;
        *(float4*)(C + (m0 + ty * 4 + mi) * 384 + n0 + tx * 4) = cv;
    }
}

// ---------------- single-step GRU with h0=0 (stage 3; attn over T=1 is identity) ----
__global__ void gru_single(const float* __restrict__ gi, const float* __restrict__ bhh,
                           float* __restrict__ lg)
{
    int idx = blockIdx.x * 256 + threadIdx.x;
    int s = idx >> 7, j = idx & 127;
    const float* gp = gi + (size_t)s * 384;
    float r = sigmoidf_(__ldg(gp + j) + __ldg(bhh + j));
    float z = sigmoidf_(__ldg(gp + 128 + j) + __ldg(bhh + 128 + j));
    float n = tanhf_(__ldg(gp + 256 + j) + r * __ldg(bhh + 256 + j));
    lg[idx] = (1.f - z) * n;
}

// ---------------- attention pooling over T (stage 4) ----------------
__global__ void __launch_bounds__(128) attn_pool(
    const float* __restrict__ hist, const float* __restrict__ aw,
    const float* __restrict__ ab, float* __restrict__ out, int T)
{
    __shared__ float red[4];
    __shared__ float sc[32];
    int s = blockIdx.x, d = threadIdx.x;
    const float* hp = hist + (size_t)s * T * 128;
    float a = __ldg(aw + d);
    float ab0 = __ldg(ab);
    for (int t = 0; t < T; t++) {
        float v = hp[t * 128 + d] * a;
        float sum = blockReduceSum128(v, red);
        if (d == 0) sc[t] = sum + ab0;
    }
    __syncthreads();
    float m = -1e30f;
    for (int t = 0; t < T; t++) m = fmaxf(m, sc[t]);
    float Z = 0.f, acc = 0.f;
    for (int t = 0; t < T; t++) {
        float w = __expf(sc[t] - m);
        Z += w;
        acc = fmaf(w, hp[t * 128 + d], acc);
    }
    out[(size_t)s * 128 + d] = acc / Z;
}

// ---------------- GAT prep ----------------
__global__ void __launch_bounds__(128) gat_prep(
    const float* __restrict__ Hin, int rstride,
    const float* __restrict__ W, const float* __restrict__ a,
    float* __restrict__ Wh, float* __restrict__ s12, int M)
{
    __shared__ float red[4];
    int m = blockIdx.x, n = threadIdx.x;
    const float* hr = Hin + (size_t)m * rstride;
    float acc = 0.f;
    #pragma unroll 8
    for (int k = 0; k < 128; k++) acc = fmaf(__ldg(hr + k), W[k * 128 + n], acc);
    Wh[(size_t)m * 128 + n] = acc;
    float s1 = blockReduceSum128(acc * __ldg(a + n), red);
    float s2 = blockReduceSum128(acc * __ldg(a + 128 + n), red);
    if (n == 0) { s12[m] = s1; s12[M + m] = s2; }
}

// ---------------- GAT intra attention ----------------
__global__ void __launch_bounds__(128) gat_intra_attn(
    const float* __restrict__ Wh, const float* __restrict__ s12,
    const int* __restrict__ sect, float* __restrict__ out)
{
    __shared__ float red[4];
    __shared__ int lst[2048];
    __shared__ float wgt[2048];
    __shared__ int cnt;
    int i = blockIdx.x, d = threadIdx.x;
    if (d == 0) cnt = 0;
    __syncthreads();
    int si = __ldg(sect + i);
    for (int j = d; j < 2048; j += 128)
        if (__ldg(sect + j) == si) { int p = atomicAdd(&cnt, 1); lst[p] = j; }
    __syncthreads();
    int n = cnt;
    float s1i = s12[i];
    float lm = -1e30f;
    for (int p = d; p < n; p += 128) {
        float e = s1i + s12[2048 + lst[p]];
        e = e >= 0.f ? e : 0.2f * e;
        lm = fmaxf(lm, e);
    }
    #pragma unroll
    for (int o = 16; o; o >>= 1) lm = fmaxf(lm, __shfl_xor_sync(0xffffffffu, lm, o));
    if ((d & 31) == 0) red[d >> 5] = lm;
    __syncthreads();
    float m = fmaxf(fmaxf(red[0], red[1]), fmaxf(red[2], red[3]));
    __syncthreads();
    float lz = 0.f;
    for (int p = d; p < n; p += 128) {
        float e = s1i + s12[2048 + lst[p]];
        e = e >= 0.f ? e : 0.2f * e;
        float w = __expf(e - m);
        wgt[p] = w;
        lz += w;
    }
    float Z = blockReduceSum128(lz, red);
    float inv = __fdividef(1.f, Z);
    float acc = 0.f;
    #pragma unroll 4
    for (int p = 0; p < n; p++) acc = fmaf(wgt[p], Wh[(size_t)lst[p] * 128 + d], acc);
    acc *= inv;
    out[(size_t)i * 128 + d] = acc > 0.f ? acc : expm1f(acc);
}

// ---------------- sector mean ----------------
__global__ void __launch_bounds__(128) sector_mean(
    const float* __restrict__ lg, const int* __restrict__ sect, float* __restrict__ sec)
{
    int ns = blockIdx.x, d = threadIdx.x;
    float s = 0.f;
    int c = 0;
    for (int i = 0; i < 2048; i++) {
        if (__ldg(sect + i) == ns) { s += lg[(size_t)i * 128 + d]; c++; }
    }
    sec[ns * 128 + d] = s / fmaxf((float)c, 1.f);
}

// ---------------- GAT inter attention ----------------
__global__ void __launch_bounds__(128) gat_inter_attn(
    const float* __restrict__ Wh, const float* __restrict__ s12,
    const int* __restrict__ adj, float* __restrict__ out)
{
    __shared__ float e[16];
    int i = blockIdx.x, d = threadIdx.x;
    if (d < 16) {
        float v = s12[i] + s12[16 + d];
        v = v >= 0.f ? v : 0.2f * v;
        e[d] = (__ldg(adj + i * 16 + d) > 0) ? v : -9.0e15f;
    }
    __syncthreads();
    float m = -1e30f;
    #pragma unroll
    for (int j = 0; j < 16; j++) m = fmaxf(m, e[j]);
    float Z = 0.f, acc = 0.f;
    #pragma unroll
    for (int j = 0; j < 16; j++) {
        float w = __expf(e[j] - m);
        Z += w;
        acc = fmaf(w, Wh[j * 128 + d], acc);
    }
    acc = __fdividef(acc, Z);
    out[i * 128 + d] = acc > 0.f ? acc : expm1f(acc);
}

// ---------------- fusion + heads ----------------
__global__ void __launch_bounds__(128) fusion_heads(
    const float* __restrict__ lg, const float* __restrict__ la,
    const float* __restrict__ secout, const int* __restrict__ sect,
    const float* __restrict__ fw, const float* __restrict__ fb,
    const float* __restrict__ rw, const float* __restrict__ rb,
    const float* __restrict__ mw, const float* __restrict__ mb,
    float* __restrict__ out)
{
    __shared__ float red[4];
    int i = blockIdx.x, n = threadIdx.x;
    int si = __ldg(sect + i);
    const float* lgr = lg + (size_t)i * 128;
    const float* lar = la + (size_t)i * 128;
    const float* ser = secout + (size_t)si * 128;
    float acc = __ldg(fb + n);
    #pragma unroll 4
    for (int k = 0; k < 128; k++) acc = fmaf(__ldg(lgr + k), fw[k * 128 + n], acc);
    #pragma unroll 4
    for (int k = 0; k < 128; k++) acc = fmaf(__ldg(lar + k), fw[(128 + k) * 128 + n], acc);
    #pragma unroll 4
    for (int k = 0; k < 128; k++) acc = fmaf(__ldg(ser + k), fw[(256 + k) * 128 + n], acc);
    float r  = blockReduceSum128(acc * __ldg(rw + n), red);
    float mv = blockReduceSum128(acc * __ldg(mw + n), red);
    if (n == 0) {
        out[i]        = r + __ldg(rb);
        out[2048 + i] = sigmoidf_(mv + __ldg(mb));
    }
}

// ---------------- launch ----------------
extern "C" void kernel_launch(void* const* d_in, const int* in_sizes, int n_in,
                              void* d_out, int out_size)
{
    const float* sf    = (const float*)d_in[0];
    const int*   sect  = (const int*)d_in[1];
    const int*   adj   = (const int*)d_in[2];
    const float* g1Wih = (const float*)d_in[3];
    const float* g1Whh = (const float*)d_in[4];
    const float* g1bih = (const float*)d_in[5];
    const float* g1bhh = (const float*)d_in[6];
    const float* a1w   = (const float*)d_in[7];
    const float* a1b   = (const float*)d_in[8];
    const float* giW   = (const float*)d_in[9];
    const float* gia   = (const float*)d_in[10];
    const float* ggWih = (const float*)d_in[11];
    const float* ggWhh = (const float*)d_in[12];
    const float* ggbih = (const float*)d_in[13];
    const float* ggbhh = (const float*)d_in[14];
    const float* agw   = (const float*)d_in[15];
    const float* agb   = (const float*)d_in[16];
    const float* gaWih = (const float*)d_in[17];
    const float* gaWhh = (const float*)d_in[18];
    const float* gabih = (const float*)d_in[19];
    const float* gabhh = (const float*)d_in[20];
    const float* aaw   = (const float*)d_in[21];
    const float* aab   = (const float*)d_in[22];
    const float* geW   = (const float*)d_in[23];
    const float* gea   = (const float*)d_in[24];
    const float* fw    = (const float*)d_in[25];
    const float* fb    = (const float*)d_in[26];
    const float* rw    = (const float*)d_in[27];
    const float* rb    = (const float*)d_in[28];
    const float* mw    = (const float*)d_in[29];
    const float* mb    = (const float*)d_in[30];
    float* out = (float*)d_out;

    float *gi, *hist, *shortb, *WT1, *WiT, *WT4, *intra, *lgv, *lav, *Wh, *s12, *sec, *Wh2, *s12b, *secout;
    cudaGetSymbolAddress((void**)&gi, g_gi);
    cudaGetSymbolAddress((void**)&hist, g_hist);
    cudaGetSymbolAddress((void**)&shortb, g_short);
    cudaGetSymbolAddress((void**)&WT1, g_WT1);
    cudaGetSymbolAddress((void**)&WiT, g_WiT);
    cudaGetSymbolAddress((void**)&WT4, g_WT4);
    cudaGetSymbolAddress((void**)&intra, g_intra);
    cudaGetSymbolAddress((void**)&lgv, g_lg);
    cudaGetSymbolAddress((void**)&lav, g_la);
    cudaGetSymbolAddress((void**)&Wh, g_Wh);
    cudaGetSymbolAddress((void**)&s12, g_s12);
    cudaGetSymbolAddress((void**)&sec, g_sec);
    cudaGetSymbolAddress((void**)&Wh2, g_Wh2);
    cudaGetSymbolAddress((void**)&s12b, g_s12b);
    cudaGetSymbolAddress((void**)&secout, g_secout);

    // smem sizes (floats*4): stage1: 5*16*132 + 16*392 + 16*136 + 16*84 + 16*8
    const int smem1 = (5 * 16 * 132 + 16 * 392 + 16 * 136 + 16 * 84 + 16 * 8) * 4;  // 81920
    const int smem4 = (1 * 16 * 132 + 16 * 392 + 16 * 136) * 4;                      // 42240
    cudaFuncSetAttribute(gru_mma<5, true, true>,
                         cudaFuncAttributeMaxDynamicSharedMemorySize, smem1);

    // Stage 1: fused GRU1 + attention over 65536 sequences (T=5, F=16)
    transpose_w<<<384, 128>>>(g1Whh, WT1, 128);
    transpose_w<<<384, 16>>>(g1Wih, WiT, 16);
    transpose_w<<<384, 128>>>(gaWhh, WT4, 128);
    gru_mma<5, true, true><<<4096, 512, smem1>>>(
        sf, WiT, WT1, g1bih, g1bhh, a1w, a1b, shortb);

    // Stage 2: intra-sector GAT on last week's embedding
    gat_prep<<<2048, 128>>>(shortb + 31 * 128, 32 * 128, giW, gia, Wh, s12, 2048);
    gat_intra_attn<<<2048, 128>>>(Wh, s12, sect, intra);

    // Stage 3: lg = single-step GRU (h0=0, T=1 attn = identity)
    gemm_bias<<<dim3(2048 / 64, 6), 256>>>(intra, ggWih, ggbih, gi, 128);
    gru_single<<<1024, 256>>>(gi, ggbhh, lgv);

    // Stage 4: la = GRU over 32 weekly embeddings (T=32)
    gemm_bias<<<dim3(65536 / 64, 6), 256>>>(shortb, gaWih, gabih, gi, 128);
    gru_mma<32, false, false><<<128, 512, smem4>>>(
        gi, nullptr, WT4, nullptr, gabhh, nullptr, nullptr, hist);
    attn_pool<<<2048, 128>>>(hist, aaw, aab, lav, 32);

    // Stage 5: sector aggregation + inter-sector GAT
    sector_mean<<<16, 128>>>(lgv, sect, sec);
    gat_prep<<<16, 128>>>(sec, 128, geW, gea, Wh2, s12b, 16);
    gat_inter_attn<<<16, 128>>>(Wh2, s12b, adj, secout);

    // Stage 6: fusion + heads
    fusion_heads<<<2048, 128>>>(lgv, lav, secout, sect, fw, fb, rw, rb, mw, mb, out);
}

// round 5
// speedup vs baseline: 2.4976x; 1.2415x over previous
#include <cuda_runtime.h>
#include <math.h>

// ---------------- scratch (device globals; no allocation) ----------------
__device__ float g_gi[25165824];    // 65536 x 384
__device__ float g_hist[8388608];   // 2048 x 32 x 128
__device__ float g_short[8388608];  // 65536 x 128
__device__ float g_WT1[49152];      // Whh1^T [128][384] (tf32)
__device__ float g_WiT[6144];       // Wih1^T [16][384]  (tf32)
__device__ float g_WT4[49152];      // gaWhh^T [128][384] (tf32)
__device__ float g_intra[262144];
__device__ float g_lg[262144];
__device__ float g_la[262144];
__device__ float g_Wh[262144];
__device__ float g_s12[4096];
__device__ float g_sec[2048];
__device__ float g_Wh2[2048];
__device__ float g_s12b[32];
__device__ float g_secout[2048];

// ---------------- helpers ----------------
__device__ __forceinline__ float sigmoidf_(float x) {
    return __fdividef(1.f, 1.f + __expf(-x));
}
__device__ __forceinline__ float tanhapx_(float x) {
    float y; asm("tanh.approx.f32 %0, %1;" : "=f"(y) : "f"(x)); return y;
}
__device__ __forceinline__ float sigapx_(float x) {
    return fmaf(tanhapx_(0.5f * x), 0.5f, 0.5f);
}
__device__ __forceinline__ unsigned f2tf(float f) {
    unsigned u; asm("cvt.rna.tf32.f32 %0, %1;" : "=r"(u) : "f"(f)); return u;
}
__device__ __forceinline__ void mma_tf32(float d[4], const unsigned a[4],
                                         unsigned b0, unsigned b1) {
    asm volatile(
        "mma.sync.aligned.m16n8k8.row.col.f32.tf32.tf32.f32 "
        "{%0,%1,%2,%3},{%4,%5,%6,%7},{%8,%9},{%0,%1,%2,%3};\n"
        : "+f"(d[0]), "+f"(d[1]), "+f"(d[2]), "+f"(d[3])
        : "r"(a[0]), "r"(a[1]), "r"(a[2]), "r"(a[3]), "r"(b0), "r"(b1));
}
__device__ __forceinline__ float blockReduceSum128(float v, float* red) {
    #pragma unroll
    for (int o = 16; o; o >>= 1) v += __shfl_xor_sync(0xffffffffu, v, o);
    int w = threadIdx.x >> 5;
    if ((threadIdx.x & 31) == 0) red[w] = v;
    __syncthreads();
    float s = red[0] + red[1] + red[2] + red[3];
    __syncthreads();
    return s;
}

// ---------------- transpose W[384,K] -> WT[k*384+g], pre-converted tf32 ----------------
__global__ void transpose_w(const float* __restrict__ W, float* __restrict__ WT, int K) {
    int g = blockIdx.x, k = threadIdx.x;
    WT[k * 384 + g] = __uint_as_float(f2tf(W[g * K + k]));
}

// ---------------- tensor-core GRU recurrence, in-register gate update ----------------
// 16 seqs/CTA, 512 thr = 16 warps; warp w owns cols w*8.. of each gate block.
// Whh^T tf32 fragments in registers. tf32 h ping-pong in smem for MMA A operand.
template<int T, bool XMMA, bool FUSE>
__global__ void __launch_bounds__(512, 1) gru_mma(
    const float* __restrict__ xin,   // XMMA: x rows of 80; else gi [(seq*T+t)][384]
    const float* __restrict__ WiT,   // XMMA: [16][384] tf32
    const float* __restrict__ WT,    // [128][384] tf32
    const float* __restrict__ bih,   // XMMA only
    const float* __restrict__ bhh,
    const float* __restrict__ aw, const float* __restrict__ ab,  // FUSE only
    float* __restrict__ outp)        // FUSE: [seq][128]; else hist [(seq*T+t)][128]
{
    extern __shared__ float sm[];
    constexpr int NFP = FUSE ? T : 2;
    float* htf = sm;                       // 2 x 16x132 tf32 ping-pong
    float* hfp = htf + 2 * 16 * 132;       // fp32 h: T slots (FUSE) or 2 (ping-pong)
    float* x_s = hfp + NFP * 16 * 132;     // XMMA: 16x84 (tf32)
    float* sc_s = x_s + (XMMA ? 16 * 84 : 0);

    int tid = threadIdx.x;
    int w = tid >> 5, lane = tid & 31;
    int g = lane >> 2, tig = lane & 3;
    size_t seq0 = (size_t)blockIdx.x * 16;
    int c0 = w * 8 + 2 * tig;

    if (XMMA) {
        for (int i = tid; i < 16 * 80; i += 512) {
            float v = __ldg(xin + seq0 * 80 + i);
            x_s[(i / 80) * 84 + (i % 80)] = __uint_as_float(f2tf(v));
        }
    }
    // Whh^T fragments (pre-converted tf32, no cvt here)
    unsigned wb[16][3][2];
    #pragma unroll
    for (int kt = 0; kt < 16; kt++) {
        #pragma unroll
        for (int nt = 0; nt < 3; nt++) {
            int col = nt * 128 + w * 8 + g;
            wb[kt][nt][0] = __float_as_uint(__ldg(WT + (kt * 8 + tig) * 384 + col));
            wb[kt][nt][1] = __float_as_uint(__ldg(WT + (kt * 8 + tig + 4) * 384 + col));
        }
    }
    __syncthreads();

    for (int t = 0; t < T; t++) {
        float ar[4] = {0, 0, 0, 0}, az[4] = {0, 0, 0, 0};
        float an[4] = {0, 0, 0, 0}, agn[4] = {0, 0, 0, 0};

        if (XMMA) {
            #pragma unroll
            for (int kt = 0; kt < 2; kt++) {
                unsigned a[4];
                int kc = t * 16 + kt * 8 + tig;
                a[0] = __float_as_uint(x_s[g * 84 + kc]);
                a[1] = __float_as_uint(x_s[(g + 8) * 84 + kc]);
                a[2] = __float_as_uint(x_s[g * 84 + kc + 4]);
                a[3] = __float_as_uint(x_s[(g + 8) * 84 + kc + 4]);
                #pragma unroll
                for (int nt = 0; nt < 3; nt++) {
                    int col = nt * 128 + w * 8 + g;
                    unsigned b0 = __float_as_uint(__ldg(WiT + (kt * 8 + tig) * 384 + col));
                    unsigned b1 = __float_as_uint(__ldg(WiT + (kt * 8 + tig + 4) * 384 + col));
                    mma_tf32(nt == 0 ? ar : (nt == 1 ? az : agn), a, b0, b1);
                }
            }
        }
        if (t > 0) {
            const float* hp = htf + ((t - 1) & 1) * (16 * 132);
            #pragma unroll
            for (int kt = 0; kt < 16; kt++) {
                unsigned a[4];
                int kc = kt * 8 + tig;
                a[0] = __float_as_uint(hp[g * 132 + kc]);
                a[1] = __float_as_uint(hp[(g + 8) * 132 + kc]);
                a[2] = __float_as_uint(hp[g * 132 + kc + 4]);
                a[3] = __float_as_uint(hp[(g + 8) * 132 + kc + 4]);
                mma_tf32(ar, a, wb[kt][0][0], wb[kt][0][1]);
                mma_tf32(az, a, wb[kt][1][0], wb[kt][1][1]);
                mma_tf32(an, a, wb[kt][2][0], wb[kt][2][1]);
            }
        }
        // in-register gate update on fragments: d[0..3] = (g,c0),(g,c0+1),(g+8,c0),(g+8,c0+1)
        {
            float* hout = hfp + (FUSE ? t : (t & 1)) * (16 * 132);
            const float* hprev = hfp + (FUSE ? (t > 0 ? t - 1 : 0) : ((t - 1) & 1)) * (16 * 132);
            float* ht = htf + (t & 1) * (16 * 132);
            float2 bhr2 = *(const float2*)(bhh + c0);
            float2 bhz2 = *(const float2*)(bhh + 128 + c0);
            float2 bhn2 = *(const float2*)(bhh + 256 + c0);
            float2 bir2, biz2, bin2;
            if (XMMA) {
                bir2 = *(const float2*)(bih + c0);
                biz2 = *(const float2*)(bih + 128 + c0);
                bin2 = *(const float2*)(bih + 256 + c0);
            }
            #pragma unroll
            for (int half = 0; half < 2; half++) {
                int row = half ? g + 8 : g;
                int e = half * 2;
                float gr0 = ar[e] + bhr2.x, gr1 = ar[e + 1] + bhr2.y;
                float gz0 = az[e] + bhz2.x, gz1 = az[e + 1] + bhz2.y;
                float gn0 = an[e] + bhn2.x, gn1 = an[e + 1] + bhn2.y;
                float in0, in1;
                if (XMMA) {
                    gr0 += bir2.x; gr1 += bir2.y;
                    gz0 += biz2.x; gz1 += biz2.y;
                    in0 = agn[e] + bin2.x; in1 = agn[e + 1] + bin2.y;
                } else {
                    const float* gp = xin + ((seq0 + row) * T + t) * 384;
                    float2 grr = *(const float2*)(gp + c0);
                    float2 gzz = *(const float2*)(gp + 128 + c0);
                    float2 gnn = *(const float2*)(gp + 256 + c0);
                    gr0 += grr.x; gr1 += grr.y;
                    gz0 += gzz.x; gz1 += gzz.y;
                    in0 = gnn.x; in1 = gnn.y;
                }
                float r0 = sigapx_(gr0), r1 = sigapx_(gr1);
                float z0 = sigapx_(gz0), z1 = sigapx_(gz1);
                float n0 = tanhapx_(fmaf(r0, gn0, in0));
                float n1 = tanhapx_(fmaf(r1, gn1, in1));
                float h0, h1;
                if (t == 0) {
                    h0 = (1.f - z0) * n0;
                    h1 = (1.f - z1) * n1;
                } else {
                    float2 hp2 = *(const float2*)(hprev + row * 132 + c0);
                    h0 = fmaf(z0, hp2.x - n0, n0);
                    h1 = fmaf(z1, hp2.y - n1, n1);
                }
                *(float2*)(hout + row * 132 + c0) = make_float2(h0, h1);
                *(float2*)(ht + row * 132 + c0) =
                    make_float2(__uint_as_float(f2tf(h0)), __uint_as_float(f2tf(h1)));
                if (!FUSE) {
                    float2 hv = make_float2(h0, h1);
                    *(float2*)(outp + ((seq0 + row) * T + t) * 128 + c0) = hv;
                }
            }
        }
        __syncthreads();
    }

    if (FUSE) {
        // fused attention pooling over T
        float ab0 = __ldg(ab);
        {
            int s = w;  // 16 warps = 16 seqs
            for (int t = 0; t < T; t++) {
                float v = 0.f;
                #pragma unroll
                for (int q = 0; q < 4; q++) {
                    int j = lane + 32 * q;
                    v = fmaf(hfp[t * 16 * 132 + s * 132 + j], __ldg(aw + j), v);
                }
                #pragma unroll
                for (int o = 16; o; o >>= 1) v += __shfl_xor_sync(0xffffffffu, v, o);
                if (lane == 0) sc_s[s * 8 + t] = v + ab0;
            }
        }
        __syncthreads();
        int j = tid & 127, sb = tid >> 7;
        #pragma unroll
        for (int i = 0; i < 4; i++) {
            int s = sb + i * 4;
            float m = -1e30f;
            #pragma unroll
            for (int t = 0; t < T; t++) m = fmaxf(m, sc_s[s * 8 + t]);
            float Z = 0.f, acc = 0.f;
            #pragma unroll
            for (int t = 0; t < T; t++) {
                float wt = __expf(sc_s[s * 8 + t] - m);
                Z += wt;
                acc = fmaf(wt, hfp[t * 16 * 132 + s * 132 + j], acc);
            }
            outp[(seq0 + s) * 128 + j] = acc / Z;
        }
    }
}

// ---------------- tf32 GEMM: C[M,384] = A[M,128] @ W[384,128]^T + bias ----------------
// grid (M/64, 6), 256 threads = 8 warps (4m x 2n); whole K=128 staged in smem.
__global__ void __launch_bounds__(256) gemm_tf32(
    const float* __restrict__ A, const float* __restrict__ W,
    const float* __restrict__ bias, float* __restrict__ C)
{
    extern __shared__ float gs[];
    float* As = gs;             // 64 x 132
    float* Ws = gs + 64 * 132;  // 64 x 132
    int tid = threadIdx.x;
    size_t m0 = (size_t)blockIdx.x * 64;
    int n0 = blockIdx.y * 64;
    for (int i = tid; i < 2048; i += 256) {
        int r = i >> 5, c4 = (i & 31) * 4;
        float4 av = *(const float4*)(A + (m0 + r) * 128 + c4);
        float4 wv = *(const float4*)(W + (size_t)(n0 + r) * 128 + c4);
        av.x = __uint_as_float(f2tf(av.x)); av.y = __uint_as_float(f2tf(av.y));
        av.z = __uint_as_float(f2tf(av.z)); av.w = __uint_as_float(f2tf(av.w));
        wv.x = __uint_as_float(f2tf(wv.x)); wv.y = __uint_as_float(f2tf(wv.y));
        wv.z = __uint_as_float(f2tf(wv.z)); wv.w = __uint_as_float(f2tf(wv.w));
        *(float4*)(As + r * 132 + c4) = av;
        *(float4*)(Ws + r * 132 + c4) = wv;
    }
    __syncthreads();
    int w = tid >> 5, lane = tid & 31;
    int wm = w & 3, wn = w >> 2;
    int g = lane >> 2, tig = lane & 3;
    int mrow = wm * 16, nbase = wn * 32;
    float d[4][4] = {};
    #pragma unroll
    for (int k0 = 0; k0 < 128; k0 += 8) {
        unsigned a[4];
        a[0] = __float_as_uint(As[(mrow + g) * 132 + k0 + tig]);
        a[1] = __float_as_uint(As[(mrow + g + 8) * 132 + k0 + tig]);
        a[2] = __float_as_uint(As[(mrow + g) * 132 + k0 + tig + 4]);
        a[3] = __float_as_uint(As[(mrow + g + 8) * 132 + k0 + tig + 4]);
        #pragma unroll
        for (int f = 0; f < 4; f++) {
            unsigned b0 = __float_as_uint(Ws[(nbase + f * 8 + g) * 132 + k0 + tig]);
            unsigned b1 = __float_as_uint(Ws[(nbase + f * 8 + g) * 132 + k0 + tig + 4]);
            mma_tf32(d[f], a, b0, b1);
        }
    }
    #pragma unroll
    for (int f = 0; f < 4; f++) {
        int col = n0 + nbase + f * 8 + 2 * tig;
        float2 b2 = *(const float2*)(bias + col);
        *(float2*)(C + (m0 + mrow + g) * 384 + col) =
            make_float2(d[f][0] + b2.x, d[f][1] + b2.y);
        *(float2*)(C + (m0 + mrow + g + 8) * 384 + col) =
            make_float2(d[f][2] + b2.x, d[f][3] + b2.y);
    }
}

// ---------------- single-step GRU with h0=0 (stage 3) ----------------
__global__ void gru_single(const float* __restrict__ gi, const float* __restrict__ bhh,
                           float* __restrict__ lg)
{
    int idx = blockIdx.x * 256 + threadIdx.x;
    int s = idx >> 7, j = idx & 127;
    const float* gp = gi + (size_t)s * 384;
    float r = sigmoidf_(__ldg(gp + j) + __ldg(bhh + j));
    float z = sigmoidf_(__ldg(gp + 128 + j) + __ldg(bhh + 128 + j));
    float n = tanhf(__ldg(gp + 256 + j) + r * __ldg(bhh + 256 + j));
    lg[idx] = (1.f - z) * n;
}

// ---------------- attention pooling over T (stage 4) ----------------
__global__ void __launch_bounds__(128) attn_pool(
    const float* __restrict__ hist, const float* __restrict__ aw,
    const float* __restrict__ ab, float* __restrict__ out, int T)
{
    __shared__ float red[4];
    __shared__ float sc[32];
    int s = blockIdx.x, d = threadIdx.x;
    const float* hp = hist + (size_t)s * T * 128;
    float a = __ldg(aw + d);
    float ab0 = __ldg(ab);
    for (int t = 0; t < T; t++) {
        float v = hp[t * 128 + d] * a;
        float sum = blockReduceSum128(v, red);
        if (d == 0) sc[t] = sum + ab0;
    }
    __syncthreads();
    float m = -1e30f;
    for (int t = 0; t < T; t++) m = fmaxf(m, sc[t]);
    float Z = 0.f, acc = 0.f;
    for (int t = 0; t < T; t++) {
        float w = __expf(sc[t] - m);
        Z += w;
        acc = fmaf(w, hp[t * 128 + d], acc);
    }
    out[(size_t)s * 128 + d] = acc / Z;
}

// ---------------- GAT prep ----------------
__global__ void __launch_bounds__(128) gat_prep(
    const float* __restrict__ Hin, int rstride,
    const float* __restrict__ W, const float* __restrict__ a,
    float* __restrict__ Wh, float* __restrict__ s12, int M)
{
    __shared__ float red[4];
    int m = blockIdx.x, n = threadIdx.x;
    const float* hr = Hin + (size_t)m * rstride;
    float acc = 0.f;
    #pragma unroll 8
    for (int k = 0; k < 128; k++) acc = fmaf(__ldg(hr + k), W[k * 128 + n], acc);
    Wh[(size_t)m * 128 + n] = acc;
    float s1 = blockReduceSum128(acc * __ldg(a + n), red);
    float s2 = blockReduceSum128(acc * __ldg(a + 128 + n), red);
    if (n == 0) { s12[m] = s1; s12[M + m] = s2; }
}

// ---------------- GAT intra attention ----------------
__global__ void __launch_bounds__(128) gat_intra_attn(
    const float* __restrict__ Wh, const float* __restrict__ s12,
    const int* __restrict__ sect, float* __restrict__ out)
{
    __shared__ float red[4];
    __shared__ int lst[2048];
    __shared__ float wgt[2048];
    __shared__ int cnt;
    int i = blockIdx.x, d = threadIdx.x;
    if (d == 0) cnt = 0;
    __syncthreads();
    int si = __ldg(sect + i);
    for (int j = d; j < 2048; j += 128)
        if (__ldg(sect + j) == si) { int p = atomicAdd(&cnt, 1); lst[p] = j; }
    __syncthreads();
    int n = cnt;
    float s1i = s12[i];
    float lm = -1e30f;
    for (int p = d; p < n; p += 128) {
        float e = s1i + s12[2048 + lst[p]];
        e = e >= 0.f ? e : 0.2f * e;
        lm = fmaxf(lm, e);
    }
    #pragma unroll
    for (int o = 16; o; o >>= 1) lm = fmaxf(lm, __shfl_xor_sync(0xffffffffu, lm, o));
    if ((d & 31) == 0) red[d >> 5] = lm;
    __syncthreads();
    float m = fmaxf(fmaxf(red[0], red[1]), fmaxf(red[2], red[3]));
    __syncthreads();
    float lz = 0.f;
    for (int p = d; p < n; p += 128) {
        float e = s1i + s12[2048 + lst[p]];
        e = e >= 0.f ? e : 0.2f * e;
        float w = __expf(e - m);
        wgt[p] = w;
        lz += w;
    }
    float Z = blockReduceSum128(lz, red);
    float inv = __fdividef(1.f, Z);
    float acc = 0.f;
    #pragma unroll 4
    for (int p = 0; p < n; p++) acc = fmaf(wgt[p], Wh[(size_t)lst[p] * 128 + d], acc);
    acc *= inv;
    out[(size_t)i * 128 + d] = acc > 0.f ? acc : expm1f(acc);
}

// ---------------- sector mean ----------------
__global__ void __launch_bounds__(128) sector_mean(
    const float* __restrict__ lg, const int* __restrict__ sect, float* __restrict__ sec)
{
    int ns = blockIdx.x, d = threadIdx.x;
    float s = 0.f;
    int c = 0;
    for (int i = 0; i < 2048; i++) {
        if (__ldg(sect + i) == ns) { s += lg[(size_t)i * 128 + d]; c++; }
    }
    sec[ns * 128 + d] = s / fmaxf((float)c, 1.f);
}

// ---------------- GAT inter attention ----------------
__global__ void __launch_bounds__(128) gat_inter_attn(
    const float* __restrict__ Wh, const float* __restrict__ s12,
    const int* __restrict__ adj, float* __restrict__ out)
{
    __shared__ float e[16];
    int i = blockIdx.x, d = threadIdx.x;
    if (d < 16) {
        float v = s12[i] + s12[16 + d];
        v = v >= 0.f ? v : 0.2f * v;
        e[d] = (__ldg(adj + i * 16 + d) > 0) ? v : -9.0e15f;
    }
    __syncthreads();
    float m = -1e30f;
    #pragma unroll
    for (int j = 0; j < 16; j++) m = fmaxf(m, e[j]);
    float Z = 0.f, acc = 0.f;
    #pragma unroll
    for (int j = 0; j < 16; j++) {
        float w = __expf(e[j] - m);
        Z += w;
        acc = fmaf(w, Wh[j * 128 + d], acc);
    }
    acc = __fdividef(acc, Z);
    out[i * 128 + d] = acc > 0.f ? acc : expm1f(acc);
}

// ---------------- fusion + heads ----------------
__global__ void __launch_bounds__(128) fusion_heads(
    const float* __restrict__ lg, const float* __restrict__ la,
    const float* __restrict__ secout, const int* __restrict__ sect,
    const float* __restrict__ fw, const float* __restrict__ fb,
    const float* __restrict__ rw, const float* __restrict__ rb,
    const float* __restrict__ mw, const float* __restrict__ mb,
    float* __restrict__ out)
{
    __shared__ float red[4];
    int i = blockIdx.x, n = threadIdx.x;
    int si = __ldg(sect + i);
    const float* lgr = lg + (size_t)i * 128;
    const float* lar = la + (size_t)i * 128;
    const float* ser = secout + (size_t)si * 128;
    float acc = __ldg(fb + n);
    #pragma unroll 4
    for (int k = 0; k < 128; k++) acc = fmaf(__ldg(lgr + k), fw[k * 128 + n], acc);
    #pragma unroll 4
    for (int k = 0; k < 128; k++) acc = fmaf(__ldg(lar + k), fw[(128 + k) * 128 + n], acc);
    #pragma unroll 4
    for (int k = 0; k < 128; k++) acc = fmaf(__ldg(ser + k), fw[(256 + k) * 128 + n], acc);
    float r  = blockReduceSum128(acc * __ldg(rw + n), red);
    float mv = blockReduceSum128(acc * __ldg(mw + n), red);
    if (n == 0) {
        out[i]        = r + __ldg(rb);
        out[2048 + i] = sigmoidf_(mv + __ldg(mb));
    }
}

// ---------------- launch ----------------
extern "C" void kernel_launch(void* const* d_in, const int* in_sizes, int n_in,
                              void* d_out, int out_size)
{
    const float* sf    = (const float*)d_in[0];
    const int*   sect  = (const int*)d_in[1];
    const int*   adj   = (const int*)d_in[2];
    const float* g1Wih = (const float*)d_in[3];
    const float* g1Whh = (const float*)d_in[4];
    const float* g1bih = (const float*)d_in[5];
    const float* g1bhh = (const float*)d_in[6];
    const float* a1w   = (const float*)d_in[7];
    const float* a1b   = (const float*)d_in[8];
    const float* giW   = (const float*)d_in[9];
    const float* gia   = (const float*)d_in[10];
    const float* ggWih = (const float*)d_in[11];
    const float* ggWhh = (const float*)d_in[12];
    const float* ggbih = (const float*)d_in[13];
    const float* ggbhh = (const float*)d_in[14];
    const float* agw   = (const float*)d_in[15];
    const float* agb   = (const float*)d_in[16];
    const float* gaWih = (const float*)d_in[17];
    const float* gaWhh = (const float*)d_in[18];
    const float* gabih = (const float*)d_in[19];
    const float* gabhh = (const float*)d_in[20];
    const float* aaw   = (const float*)d_in[21];
    const float* aab   = (const float*)d_in[22];
    const float* geW   = (const float*)d_in[23];
    const float* gea   = (const float*)d_in[24];
    const float* fw    = (const float*)d_in[25];
    const float* fb    = (const float*)d_in[26];
    const float* rw    = (const float*)d_in[27];
    const float* rb    = (const float*)d_in[28];
    const float* mw    = (const float*)d_in[29];
    const float* mb    = (const float*)d_in[30];
    float* out = (float*)d_out;

    float *gi, *hist, *shortb, *WT1, *WiT, *WT4, *intra, *lgv, *lav, *Wh, *s12, *sec, *Wh2, *s12b, *secout;
    cudaGetSymbolAddress((void**)&gi, g_gi);
    cudaGetSymbolAddress((void**)&hist, g_hist);
    cudaGetSymbolAddress((void**)&shortb, g_short);
    cudaGetSymbolAddress((void**)&WT1, g_WT1);
    cudaGetSymbolAddress((void**)&WiT, g_WiT);
    cudaGetSymbolAddress((void**)&WT4, g_WT4);
    cudaGetSymbolAddress((void**)&intra, g_intra);
    cudaGetSymbolAddress((void**)&lgv, g_lg);
    cudaGetSymbolAddress((void**)&lav, g_la);
    cudaGetSymbolAddress((void**)&Wh, g_Wh);
    cudaGetSymbolAddress((void**)&s12, g_s12);
    cudaGetSymbolAddress((void**)&sec, g_sec);
    cudaGetSymbolAddress((void**)&Wh2, g_Wh2);
    cudaGetSymbolAddress((void**)&s12b, g_s12b);
    cudaGetSymbolAddress((void**)&secout, g_secout);

    const int smem1 = (2 * 16 * 132 + 5 * 16 * 132 + 16 * 84 + 16 * 8) * 4;  // 65024
    const int smem4 = (2 * 16 * 132 + 2 * 16 * 132) * 4;                      // 33792
    const int smemG = 2 * 64 * 132 * 4;                                       // 67584
    cudaFuncSetAttribute(gru_mma<5, true, true>,
                         cudaFuncAttributeMaxDynamicSharedMemorySize, smem1);
    cudaFuncSetAttribute(gemm_tf32,
                         cudaFuncAttributeMaxDynamicSharedMemorySize, smemG);

    // Stage 1: fused GRU1 + attention over 65536 sequences (T=5, F=16)
    transpose_w<<<384, 128>>>(g1Whh, WT1, 128);
    transpose_w<<<384, 16>>>(g1Wih, WiT, 16);
    transpose_w<<<384, 128>>>(gaWhh, WT4, 128);
    gru_mma<5, true, true><<<4096, 512, smem1>>>(
        sf, WiT, WT1, g1bih, g1bhh, a1w, a1b, shortb);

    // Stage 2: intra-sector GAT on last week's embedding
    gat_prep<<<2048, 128>>>(shortb + 31 * 128, 32 * 128, giW, gia, Wh, s12, 2048);
    gat_intra_attn<<<2048, 128>>>(Wh, s12, sect, intra);

    // Stage 3: lg = single-step GRU (h0=0, T=1 attn = identity)
    gemm_tf32<<<dim3(2048 / 64, 6), 256, smemG>>>(intra, ggWih, ggbih, gi);
    gru_single<<<1024, 256>>>(gi, ggbhh, lgv);

    // Stage 4: la = GRU over 32 weekly embeddings (T=32)
    gemm_tf32<<<dim3(65536 / 64, 6), 256, smemG>>>(shortb, gaWih, gabih, gi);
    gru_mma<32, false, false><<<128, 512, smem4>>>(
        gi, nullptr, WT4, nullptr, gabhh, nullptr, nullptr, hist);
    attn_pool<<<2048, 128>>>(hist, aaw, aab, lav, 32);

    // Stage 5: sector aggregation + inter-sector GAT
    sector_mean<<<16, 128>>>(lgv, sect, sec);
    gat_prep<<<16, 128>>>(sec, 128, geW, gea, Wh2, s12b, 16);
    gat_inter_attn<<<16, 128>>>(Wh2, s12b, adj, secout);

    // Stage 6: fusion + heads
    fusion_heads<<<2048, 128>>>(lgv, lav, secout, sect, fw, fb, rw, rb, mw, mb, out);
}

// round 6
// speedup vs baseline: 3.5212x; 1.4099x over previous
#include <cuda_runtime.h>
#include <cuda_bf16.h>
#include <math.h>

// ---------------- scratch (device globals; no allocation) ----------------
__device__ float g_gi[25165824];    // 65536 x 384
__device__ float g_short[8388608];  // 65536 x 128
__device__ float g_WB1[24576];      // Whh1 bf16 [384][128] (as float storage)
__device__ float g_WiB[3072];       // Wih1 bf16 [384][16]
__device__ float g_WB4[24576];      // gaWhh bf16 [384][128]
__device__ float g_intra[262144];
__device__ float g_lg[262144];
__device__ float g_la[262144];
__device__ float g_Wh[262144];
__device__ float g_s12[4096];
__device__ float g_sec[2048];
__device__ float g_Wh2[2048];
__device__ float g_s12b[32];
__device__ float g_secout[2048];

// ---------------- helpers ----------------
__device__ __forceinline__ float sigmoidf_(float x) {
    return __fdividef(1.f, 1.f + __expf(-x));
}
__device__ __forceinline__ float tanhapx_(float x) {
    float y; asm("tanh.approx.f32 %0, %1;" : "=f"(y) : "f"(x)); return y;
}
__device__ __forceinline__ float sigapx_(float x) {
    return fmaf(tanhapx_(0.5f * x), 0.5f, 0.5f);
}
__device__ __forceinline__ void mma_bf16(float d[4], unsigned a0, unsigned a1,
                                         unsigned a2, unsigned a3,
                                         unsigned b0, unsigned b1) {
    asm volatile(
        "mma.sync.aligned.m16n8k16.row.col.f32.bf16.bf16.f32 "
        "{%0,%1,%2,%3},{%4,%5,%6,%7},{%8,%9},{%0,%1,%2,%3};\n"
        : "+f"(d[0]), "+f"(d[1]), "+f"(d[2]), "+f"(d[3])
        : "r"(a0), "r"(a1), "r"(a2), "r"(a3), "r"(b0), "r"(b1));
}
__device__ __forceinline__ float blockReduceSum128(float v, float* red) {
    #pragma unroll
    for (int o = 16; o; o >>= 1) v += __shfl_xor_sync(0xffffffffu, v, o);
    int w = threadIdx.x >> 5;
    if ((threadIdx.x & 31) == 0) red[w] = v;
    __syncthreads();
    float s = red[0] + red[1] + red[2] + red[3];
    __syncthreads();
    return s;
}

// ---------------- fp32 -> bf16 convert ----------------
__global__ void conv_bf16(const float* __restrict__ W, __nv_bfloat16* __restrict__ O, int n) {
    int i = blockIdx.x * 256 + threadIdx.x;
    if (i < n) O[i] = __float2bfloat16(W[i]);
}

// ---------------- bf16 tensor-core GRU, fused attention pooling ----------------
// 16 seqs/CTA, 512 thr = 16 warps; warp w owns cols w*8.. of each gate block.
// Whh bf16 B-frags in registers (48). Full T-history of h kept as bf16 in smem.
template<int T, bool XMMA>
__global__ void __launch_bounds__(512, 1) gru_mma(
    const float* __restrict__ xin,          // XMMA: x rows of 80; else gi [(seq*T+t)][384]
    const __nv_bfloat16* __restrict__ WiB,  // XMMA: Wih bf16 [384][16]
    const __nv_bfloat16* __restrict__ WB,   // Whh bf16 [384][128]
    const float* __restrict__ bih,          // XMMA only
    const float* __restrict__ bhh,
    const float* __restrict__ aw, const float* __restrict__ ab,
    float* __restrict__ outp)               // [seq][128] pooled
{
    extern __shared__ char smc[];
    __nv_bfloat16* hsm = (__nv_bfloat16*)smc;           // [T][16][136]
    __nv_bfloat16* x_b = hsm + T * 16 * 136;            // XMMA: [16][88]
    float* sc_s = (float*)(x_b + (XMMA ? 16 * 88 : 0)); // [16][T]

    int tid = threadIdx.x;
    int w = tid >> 5, lane = tid & 31;
    int g = lane >> 2, tig = lane & 3;
    size_t seq0 = (size_t)blockIdx.x * 16;
    int c0 = w * 8 + 2 * tig;

    if (XMMA) {
        for (int i = tid; i < 16 * 80; i += 512)
            x_b[(i / 80) * 88 + (i % 80)] = __float2bfloat16(__ldg(xin + seq0 * 80 + i));
    }
    // Whh bf16 B-fragments: wb[kt][gate][reg], col = gate*128 + w*8 + g
    unsigned wb[8][3][2];
    #pragma unroll
    for (int kt = 0; kt < 8; kt++) {
        #pragma unroll
        for (int nt = 0; nt < 3; nt++) {
            const __nv_bfloat16* p = WB + (size_t)(nt * 128 + w * 8 + g) * 128 + kt * 16;
            wb[kt][nt][0] = *(const unsigned*)(p + 2 * tig);
            wb[kt][nt][1] = *(const unsigned*)(p + 8 + 2 * tig);
        }
    }
    unsigned wbi[3][2];
    if (XMMA) {
        #pragma unroll
        for (int nt = 0; nt < 3; nt++) {
            const __nv_bfloat16* p = WiB + (size_t)(nt * 128 + w * 8 + g) * 16;
            wbi[nt][0] = *(const unsigned*)(p + 2 * tig);
            wbi[nt][1] = *(const unsigned*)(p + 8 + 2 * tig);
        }
    }
    float2 bhr2 = *(const float2*)(bhh + c0);
    float2 bhz2 = *(const float2*)(bhh + 128 + c0);
    float2 bhn2 = *(const float2*)(bhh + 256 + c0);
    float2 bir2 = {0, 0}, biz2 = {0, 0}, bin2 = {0, 0};
    if (XMMA) {
        bir2 = *(const float2*)(bih + c0);
        biz2 = *(const float2*)(bih + 128 + c0);
        bin2 = *(const float2*)(bih + 256 + c0);
    }
    __syncthreads();

    for (int t = 0; t < T; t++) {
        float ra[4] = {0, 0, 0, 0}, rb[4] = {0, 0, 0, 0};
        float za[4] = {0, 0, 0, 0}, zb[4] = {0, 0, 0, 0};
        float na[4] = {0, 0, 0, 0}, nb[4] = {0, 0, 0, 0};
        float gn_[4] = {0, 0, 0, 0};
        float2 pgr[2], pgz[2], pgn[2];

        if (!XMMA) {
            // prefetch gi early so latency overlaps the MMA phase
            #pragma unroll
            for (int hh = 0; hh < 2; hh++) {
                int row = hh ? g + 8 : g;
                const float* gp = xin + ((seq0 + row) * (size_t)T + t) * 384;
                pgr[hh] = *(const float2*)(gp + c0);
                pgz[hh] = *(const float2*)(gp + 128 + c0);
                pgn[hh] = *(const float2*)(gp + 256 + c0);
            }
        } else {
            // gi = x @ Wih^T (single k16 MMA per gate)
            int kc = t * 16 + 2 * tig;
            unsigned a0 = *(const unsigned*)(x_b + g * 88 + kc);
            unsigned a1 = *(const unsigned*)(x_b + (g + 8) * 88 + kc);
            unsigned a2 = *(const unsigned*)(x_b + g * 88 + kc + 8);
            unsigned a3 = *(const unsigned*)(x_b + (g + 8) * 88 + kc + 8);
            mma_bf16(ra, a0, a1, a2, a3, wbi[0][0], wbi[0][1]);
            mma_bf16(za, a0, a1, a2, a3, wbi[1][0], wbi[1][1]);
            mma_bf16(gn_, a0, a1, a2, a3, wbi[2][0], wbi[2][1]);
        }
        if (t > 0) {
            const __nv_bfloat16* hb = hsm + (size_t)(t - 1) * 16 * 136;
            #pragma unroll
            for (int kt = 0; kt < 8; kt++) {
                int kc = kt * 16 + 2 * tig;
                unsigned a0 = *(const unsigned*)(hb + g * 136 + kc);
                unsigned a1 = *(const unsigned*)(hb + (g + 8) * 136 + kc);
                unsigned a2 = *(const unsigned*)(hb + g * 136 + kc + 8);
                unsigned a3 = *(const unsigned*)(hb + (g + 8) * 136 + kc + 8);
                if (kt & 1) {
                    mma_bf16(rb, a0, a1, a2, a3, wb[kt][0][0], wb[kt][0][1]);
                    mma_bf16(zb, a0, a1, a2, a3, wb[kt][1][0], wb[kt][1][1]);
                    mma_bf16(nb, a0, a1, a2, a3, wb[kt][2][0], wb[kt][2][1]);
                } else {
                    mma_bf16(ra, a0, a1, a2, a3, wb[kt][0][0], wb[kt][0][1]);
                    mma_bf16(za, a0, a1, a2, a3, wb[kt][1][0], wb[kt][1][1]);
                    mma_bf16(na, a0, a1, a2, a3, wb[kt][2][0], wb[kt][2][1]);
                }
            }
        }
        // in-register gate update on fragments
        {
            __nv_bfloat16* hcur = hsm + (size_t)t * 16 * 136;
            const __nv_bfloat16* hprv = hsm + (size_t)(t > 0 ? t - 1 : 0) * 16 * 136;
            #pragma unroll
            for (int hh = 0; hh < 2; hh++) {
                int row = hh ? g + 8 : g;
                int e = hh * 2;
                float gr0 = ra[e] + rb[e] + bhr2.x, gr1 = ra[e + 1] + rb[e + 1] + bhr2.y;
                float gz0 = za[e] + zb[e] + bhz2.x, gz1 = za[e + 1] + zb[e + 1] + bhz2.y;
                float gn0 = na[e] + nb[e] + bhn2.x, gn1 = na[e + 1] + nb[e + 1] + bhn2.y;
                float in0, in1;
                if (XMMA) {
                    gr0 += bir2.x; gr1 += bir2.y;
                    gz0 += biz2.x; gz1 += biz2.y;
                    in0 = gn_[e] + bin2.x; in1 = gn_[e + 1] + bin2.y;
                } else {
                    gr0 += pgr[hh].x; gr1 += pgr[hh].y;
                    gz0 += pgz[hh].x; gz1 += pgz[hh].y;
                    in0 = pgn[hh].x; in1 = pgn[hh].y;
                }
                float r0 = sigapx_(gr0), r1 = sigapx_(gr1);
                float z0 = sigapx_(gz0), z1 = sigapx_(gz1);
                float n0 = tanhapx_(fmaf(r0, gn0, in0));
                float n1 = tanhapx_(fmaf(r1, gn1, in1));
                float h0, h1;
                if (t == 0) {
                    h0 = (1.f - z0) * n0;
                    h1 = (1.f - z1) * n1;
                } else {
                    float2 hp2 = __bfloat1622float2(*(const __nv_bfloat162*)(hprv + row * 136 + c0));
                    h0 = fmaf(z0, hp2.x - n0, n0);
                    h1 = fmaf(z1, hp2.y - n1, n1);
                }
                *(__nv_bfloat162*)(hcur + row * 136 + c0) =
                    __float22bfloat162_rn(make_float2(h0, h1));
            }
        }
        __syncthreads();
    }

    // fused attention pooling over T (h history in bf16 smem)
    float ab0 = __ldg(ab);
    {
        int s = w;  // 16 warps = 16 seqs
        float awv[4];
        #pragma unroll
        for (int q = 0; q < 4; q++) awv[q] = __ldg(aw + lane + 32 * q);
        for (int t = 0; t < T; t++) {
            float v = 0.f;
            #pragma unroll
            for (int q = 0; q < 4; q++)
                v = fmaf(__bfloat162float(hsm[t * 16 * 136 + s * 136 + lane + 32 * q]), awv[q], v);
            #pragma unroll
            for (int o = 16; o; o >>= 1) v += __shfl_xor_sync(0xffffffffu, v, o);
            if (lane == 0) sc_s[s * T + t] = v + ab0;
        }
    }
    __syncthreads();
    {
        int j = tid & 127, sb = tid >> 7;
        #pragma unroll
        for (int i = 0; i < 4; i++) {
            int s = sb + i * 4;
            float m = -1e30f;
            for (int t = 0; t < T; t++) m = fmaxf(m, sc_s[s * T + t]);
            float Z = 0.f, acc = 0.f;
            for (int t = 0; t < T; t++) {
                float wt = __expf(sc_s[s * T + t] - m);
                Z += wt;
                acc = fmaf(wt, __bfloat162float(hsm[t * 16 * 136 + s * 136 + j]), acc);
            }
            outp[(seq0 + s) * 128 + j] = acc / Z;
        }
    }
}

// ---------------- bf16 GEMM: C[M,384] = A[M,128] @ W[384,128]^T + bias ----------------
// grid (M/64, 6), 256 threads = 8 warps (4m x 2n); whole K=128 in smem (bf16).
__global__ void __launch_bounds__(256) gemm_bf16(
    const float* __restrict__ A, const float* __restrict__ W,
    const float* __restrict__ bias, float* __restrict__ C)
{
    extern __shared__ char gsc[];
    __nv_bfloat16* As = (__nv_bfloat16*)gsc;  // 64 x 136
    __nv_bfloat16* Ws = As + 64 * 136;        // 64 x 136
    int tid = threadIdx.x;
    size_t m0 = (size_t)blockIdx.x * 64;
    int n0 = blockIdx.y * 64;
    for (int i = tid; i < 2048; i += 256) {
        int r = i >> 5, c4 = (i & 31) * 4;
        float4 av = *(const float4*)(A + (m0 + r) * 128 + c4);
        float4 wv = *(const float4*)(W + (size_t)(n0 + r) * 128 + c4);
        *(__nv_bfloat162*)(As + r * 136 + c4)     = __float22bfloat162_rn(make_float2(av.x, av.y));
        *(__nv_bfloat162*)(As + r * 136 + c4 + 2) = __float22bfloat162_rn(make_float2(av.z, av.w));
        *(__nv_bfloat162*)(Ws + r * 136 + c4)     = __float22bfloat162_rn(make_float2(wv.x, wv.y));
        *(__nv_bfloat162*)(Ws + r * 136 + c4 + 2) = __float22bfloat162_rn(make_float2(wv.z, wv.w));
    }
    __syncthreads();
    int w = tid >> 5, lane = tid & 31;
    int wm = w & 3, wn = w >> 2;
    int g = lane >> 2, tig = lane & 3;
    int mrow = wm * 16, nbase = wn * 32;
    float d[4][4] = {};
    #pragma unroll
    for (int k0 = 0; k0 < 128; k0 += 16) {
        int kc = k0 + 2 * tig;
        unsigned a0 = *(const unsigned*)(As + (mrow + g) * 136 + kc);
        unsigned a1 = *(const unsigned*)(As + (mrow + g + 8) * 136 + kc);
        unsigned a2 = *(const unsigned*)(As + (mrow + g) * 136 + kc + 8);
        unsigned a3 = *(const unsigned*)(As + (mrow + g + 8) * 136 + kc + 8);
        #pragma unroll
        for (int f = 0; f < 4; f++) {
            unsigned b0 = *(const unsigned*)(Ws + (nbase + f * 8 + g) * 136 + kc);
            unsigned b1 = *(const unsigned*)(Ws + (nbase + f * 8 + g) * 136 + kc + 8);
            mma_bf16(d[f], a0, a1, a2, a3, b0, b1);
        }
    }
    #pragma unroll
    for (int f = 0; f < 4; f++) {
        int col = n0 + nbase + f * 8 + 2 * tig;
        float2 b2 = *(const float2*)(bias + col);
        *(float2*)(C + (m0 + mrow + g) * 384 + col) =
            make_float2(d[f][0] + b2.x, d[f][1] + b2.y);
        *(float2*)(C + (m0 + mrow + g + 8) * 384 + col) =
            make_float2(d[f][2] + b2.x, d[f][3] + b2.y);
    }
}

// ---------------- single-step GRU with h0=0 (stage 3) ----------------
__global__ void gru_single(const float* __restrict__ gi, const float* __restrict__ bhh,
                           float* __restrict__ lg)
{
    int idx = blockIdx.x * 256 + threadIdx.x;
    int s = idx >> 7, j = idx & 127;
    const float* gp = gi + (size_t)s * 384;
    float r = sigmoidf_(__ldg(gp + j) + __ldg(bhh + j));
    float z = sigmoidf_(__ldg(gp + 128 + j) + __ldg(bhh + 128 + j));
    float n = tanhf(__ldg(gp + 256 + j) + r * __ldg(bhh + 256 + j));
    lg[idx] = (1.f - z) * n;
}

// ---------------- GAT prep ----------------
__global__ void __launch_bounds__(128) gat_prep(
    const float* __restrict__ Hin, int rstride,
    const float* __restrict__ W, const float* __restrict__ a,
    float* __restrict__ Wh, float* __restrict__ s12, int M)
{
    __shared__ float red[4];
    int m = blockIdx.x, n = threadIdx.x;
    const float* hr = Hin + (size_t)m * rstride;
    float acc = 0.f;
    #pragma unroll 8
    for (int k = 0; k < 128; k++) acc = fmaf(__ldg(hr + k), W[k * 128 + n], acc);
    Wh[(size_t)m * 128 + n] = acc;
    float s1 = blockReduceSum128(acc * __ldg(a + n), red);
    float s2 = blockReduceSum128(acc * __ldg(a + 128 + n), red);
    if (n == 0) { s12[m] = s1; s12[M + m] = s2; }
}

// ---------------- GAT intra attention ----------------
__global__ void __launch_bounds__(128) gat_intra_attn(
    const float* __restrict__ Wh, const float* __restrict__ s12,
    const int* __restrict__ sect, float* __restrict__ out)
{
    __shared__ float red[4];
    __shared__ int lst[2048];
    __shared__ float wgt[2048];
    __shared__ int cnt;
    int i = blockIdx.x, d = threadIdx.x;
    if (d == 0) cnt = 0;
    __syncthreads();
    int si = __ldg(sect + i);
    for (int j = d; j < 2048; j += 128)
        if (__ldg(sect + j) == si) { int p = atomicAdd(&cnt, 1); lst[p] = j; }
    __syncthreads();
    int n = cnt;
    float s1i = s12[i];
    float lm = -1e30f;
    for (int p = d; p < n; p += 128) {
        float e = s1i + s12[2048 + lst[p]];
        e = e >= 0.f ? e : 0.2f * e;
        lm = fmaxf(lm, e);
    }
    #pragma unroll
    for (int o = 16; o; o >>= 1) lm = fmaxf(lm, __shfl_xor_sync(0xffffffffu, lm, o));
    if ((d & 31) == 0) red[d >> 5] = lm;
    __syncthreads();
    float m = fmaxf(fmaxf(red[0], red[1]), fmaxf(red[2], red[3]));
    __syncthreads();
    float lz = 0.f;
    for (int p = d; p < n; p += 128) {
        float e = s1i + s12[2048 + lst[p]];
        e = e >= 0.f ? e : 0.2f * e;
        float w = __expf(e - m);
        wgt[p] = w;
        lz += w;
    }
    float Z = blockReduceSum128(lz, red);
    float inv = __fdividef(1.f, Z);
    float acc = 0.f;
    #pragma unroll 4
    for (int p = 0; p < n; p++) acc = fmaf(wgt[p], Wh[(size_t)lst[p] * 128 + d], acc);
    acc *= inv;
    out[(size_t)i * 128 + d] = acc > 0.f ? acc : expm1f(acc);
}

// ---------------- sector mean ----------------
__global__ void __launch_bounds__(128) sector_mean(
    const float* __restrict__ lg, const int* __restrict__ sect, float* __restrict__ sec)
{
    int ns = blockIdx.x, d = threadIdx.x;
    float s = 0.f;
    int c = 0;
    for (int i = 0; i < 2048; i++) {
        if (__ldg(sect + i) == ns) { s += lg[(size_t)i * 128 + d]; c++; }
    }
    sec[ns * 128 + d] = s / fmaxf((float)c, 1.f);
}

// ---------------- GAT inter attention ----------------
__global__ void __launch_bounds__(128) gat_inter_attn(
    const float* __restrict__ Wh, const float* __restrict__ s12,
    const int* __restrict__ adj, float* __restrict__ out)
{
    __shared__ float e[16];
    int i = blockIdx.x, d = threadIdx.x;
    if (d < 16) {
        float v = s12[i] + s12[16 + d];
        v = v >= 0.f ? v : 0.2f * v;
        e[d] = (__ldg(adj + i * 16 + d) > 0) ? v : -9.0e15f;
    }
    __syncthreads();
    float m = -1e30f;
    #pragma unroll
    for (int j = 0; j < 16; j++) m = fmaxf(m, e[j]);
    float Z = 0.f, acc = 0.f;
    #pragma unroll
    for (int j = 0; j < 16; j++) {
        float w = __expf(e[j] - m);
        Z += w;
        acc = fmaf(w, Wh[j * 128 + d], acc);
    }
    acc = __fdividef(acc, Z);
    out[i * 128 + d] = acc > 0.f ? acc : expm1f(acc);
}

// ---------------- fusion + heads ----------------
__global__ void __launch_bounds__(128) fusion_heads(
    const float* __restrict__ lg, const float* __restrict__ la,
    const float* __restrict__ secout, const int* __restrict__ sect,
    const float* __restrict__ fw, const float* __restrict__ fb,
    const float* __restrict__ rw, const float* __restrict__ rb,
    const float* __restrict__ mw, const float* __restrict__ mb,
    float* __restrict__ out)
{
    __shared__ float red[4];
    int i = blockIdx.x, n = threadIdx.x;
    int si = __ldg(sect + i);
    const float* lgr = lg + (size_t)i * 128;
    const float* lar = la + (size_t)i * 128;
    const float* ser = secout + (size_t)si * 128;
    float acc = __ldg(fb + n);
    #pragma unroll 4
    for (int k = 0; k < 128; k++) acc = fmaf(__ldg(lgr + k), fw[k * 128 + n], acc);
    #pragma unroll 4
    for (int k = 0; k < 128; k++) acc = fmaf(__ldg(lar + k), fw[(128 + k) * 128 + n], acc);
    #pragma unroll 4
    for (int k = 0; k < 128; k++) acc = fmaf(__ldg(ser + k), fw[(256 + k) * 128 + n], acc);
    float r  = blockReduceSum128(acc * __ldg(rw + n), red);
    float mv = blockReduceSum128(acc * __ldg(mw + n), red);
    if (n == 0) {
        out[i]        = r + __ldg(rb);
        out[2048 + i] = sigmoidf_(mv + __ldg(mb));
    }
}

// ---------------- launch ----------------
extern "C" void kernel_launch(void* const* d_in, const int* in_sizes, int n_in,
                              void* d_out, int out_size)
{
    const float* sf    = (const float*)d_in[0];
    const int*   sect  = (const int*)d_in[1];
    const int*   adj   = (const int*)d_in[2];
    const float* g1Wih = (const float*)d_in[3];
    const float* g1Whh = (const float*)d_in[4];
    const float* g1bih = (const float*)d_in[5];
    const float* g1bhh = (const float*)d_in[6];
    const float* a1w   = (const float*)d_in[7];
    const float* a1b   = (const float*)d_in[8];
    const float* giW   = (const float*)d_in[9];
    const float* gia   = (const float*)d_in[10];
    const float* ggWih = (const float*)d_in[11];
    const float* ggWhh = (const float*)d_in[12];
    const float* ggbih = (const float*)d_in[13];
    const float* ggbhh = (const float*)d_in[14];
    const float* agw   = (const float*)d_in[15];
    const float* agb   = (const float*)d_in[16];
    const float* gaWih = (const float*)d_in[17];
    const float* gaWhh = (const float*)d_in[18];
    const float* gabih = (const float*)d_in[19];
    const float* gabhh = (const float*)d_in[20];
    const float* aaw   = (const float*)d_in[21];
    const float* aab   = (const float*)d_in[22];
    const float* geW   = (const float*)d_in[23];
    const float* gea   = (const float*)d_in[24];
    const float* fw    = (const float*)d_in[25];
    const float* fb    = (const float*)d_in[26];
    const float* rw    = (const float*)d_in[27];
    const float* rb    = (const float*)d_in[28];
    const float* mw    = (const float*)d_in[29];
    const float* mb    = (const float*)d_in[30];
    float* out = (float*)d_out;

    float *gi, *shortb, *WB1f, *WiBf, *WB4f, *intra, *lgv, *lav, *Wh, *s12, *sec, *Wh2, *s12b, *secout;
    cudaGetSymbolAddress((void**)&gi, g_gi);
    cudaGetSymbolAddress((void**)&shortb, g_short);
    cudaGetSymbolAddress((void**)&WB1f, g_WB1);
    cudaGetSymbolAddress((void**)&WiBf, g_WiB);
    cudaGetSymbolAddress((void**)&WB4f, g_WB4);
    cudaGetSymbolAddress((void**)&intra, g_intra);
    cudaGetSymbolAddress((void**)&lgv, g_lg);
    cudaGetSymbolAddress((void**)&lav, g_la);
    cudaGetSymbolAddress((void**)&Wh, g_Wh);
    cudaGetSymbolAddress((void**)&s12, g_s12);
    cudaGetSymbolAddress((void**)&sec, g_sec);
    cudaGetSymbolAddress((void**)&Wh2, g_Wh2);
    cudaGetSymbolAddress((void**)&s12b, g_s12b);
    cudaGetSymbolAddress((void**)&secout, g_secout);
    __nv_bfloat16* WB1 = (__nv_bfloat16*)WB1f;
    __nv_bfloat16* WiB = (__nv_bfloat16*)WiBf;
    __nv_bfloat16* WB4 = (__nv_bfloat16*)WB4f;

    const int smem1 = 5 * 16 * 136 * 2 + 16 * 88 * 2 + 16 * 5 * 4;   // 24896
    const int smem4 = 32 * 16 * 136 * 2 + 16 * 32 * 4;               // 141312
    const int smemG = 2 * 64 * 136 * 2;                              // 34816
    cudaFuncSetAttribute(gru_mma<5, true>,
                         cudaFuncAttributeMaxDynamicSharedMemorySize, smem1);
    cudaFuncSetAttribute(gru_mma<32, false>,
                         cudaFuncAttributeMaxDynamicSharedMemorySize, smem4);

    // weight conversions to bf16
    conv_bf16<<<(49152 + 255) / 256, 256>>>(g1Whh, WB1, 49152);
    conv_bf16<<<(6144 + 255) / 256, 256>>>(g1Wih, WiB, 6144);
    conv_bf16<<<(49152 + 255) / 256, 256>>>(gaWhh, WB4, 49152);

    // Stage 1: fused GRU1 + attention over 65536 sequences (T=5, F=16)
    gru_mma<5, true><<<4096, 512, smem1>>>(
        sf, WiB, WB1, g1bih, g1bhh, a1w, a1b, shortb);

    // Stage 2: intra-sector GAT on last week's embedding
    gat_prep<<<2048, 128>>>(shortb + 31 * 128, 32 * 128, giW, gia, Wh, s12, 2048);
    gat_intra_attn<<<2048, 128>>>(Wh, s12, sect, intra);

    // Stage 3: lg = single-step GRU (h0=0, T=1 attn = identity)
    gemm_bf16<<<dim3(2048 / 64, 6), 256, smemG>>>(intra, ggWih, ggbih, gi);
    gru_single<<<1024, 256>>>(gi, ggbhh, lgv);

    // Stage 4: la = GRU over 32 weekly embeddings (T=32), pooling fused
    gemm_bf16<<<dim3(65536 / 64, 6), 256, smemG>>>(shortb, gaWih, gabih, gi);
    gru_mma<32, false><<<128, 512, smem4>>>(
        gi, nullptr, WB4, nullptr, gabhh, aaw, aab, lav);

    // Stage 5: sector aggregation + inter-sector GAT
    sector_mean<<<16, 128>>>(lgv, sect, sec);
    gat_prep<<<16, 128>>>(sec, 128, geW, gea, Wh2, s12b, 16);
    gat_inter_attn<<<16, 128>>>(Wh2, s12b, adj, secout);

    // Stage 6: fusion + heads
    fusion_heads<<<2048, 128>>>(lgv, lav, secout, sect, fw, fb, rw, rb, mw, mb, out);
}